// round 8
// baseline (speedup 1.0000x reference)
#include <cuda_runtime.h>

#define NN 50000
#define NE 800000
#define FULLMASK 0xffffffffu

// ---------------- static device scratch (no allocation allowed) ----------------
// NOTE: d_deg/d_cur are zero-initialized at module load and re-zeroed at the END
// of every kernel_launch (zero_kernel is the last launch). This keeps the CSR
// counters valid at entry of every invocation while freeing launch slot 0.
__device__ float d_Q [NN * 128];
__device__ float d_Kn[NN * 128];
__device__ float d_Vn[NN * 128];
__device__ float d_Ov[NN * 128];
__device__ __align__(16) int d_deg[NN];
__device__ int   d_cur[NN];
__device__ __align__(16) int d_rowptr[NN + 4];
__device__ int2  d_es[NE];      // per CSR slot: (edge id, source node)

// ---------------- CSR build ----------------
__global__ void zero_kernel(int n) {
    int i = blockIdx.x * blockDim.x + threadIdx.x;
    if (i < n) { d_deg[i] = 0; d_cur[i] = 0; }
}

__global__ void deg_kernel(const int* __restrict__ tgt, int E) {
    int e = blockIdx.x * blockDim.x + threadIdx.x;
    if (e < E) atomicAdd(&d_deg[tgt[e]], 1);
}

// single-block exclusive scan of d_deg -> d_rowptr, int4-vectorized
__global__ void scan_kernel(int n) {
    __shared__ int ssum[1024];
    int t = threadIdx.x;
    int n4 = n >> 2;
    int C = (n4 + 1023) >> 10;
    int s0 = t * C;
    int s1 = min(s0 + C, n4);
    const int4* deg4 = (const int4*)d_deg;
    int s = 0;
    for (int i = s0; i < s1; i++) {
        int4 v = deg4[i];
        s += v.x + v.y + v.z + v.w;
    }
    ssum[t] = s;
    __syncthreads();
    for (int off = 1; off < 1024; off <<= 1) {
        int v = 0;
        if (t >= off) v = ssum[t - off];
        __syncthreads();
        if (t >= off) ssum[t] += v;
        __syncthreads();
    }
    int run = (t == 0) ? 0 : ssum[t - 1];
    int4* rp4 = (int4*)d_rowptr;
    for (int i = s0; i < s1; i++) {
        int4 v = deg4[i];
        int4 r;
        r.x = run; run += v.x;
        r.y = run; run += v.y;
        r.z = run; run += v.z;
        r.w = run; run += v.w;
        rp4[i] = r;
    }
    if (t == 1023) {
        int run2 = ssum[1023];
        for (int i = n4 * 4; i < n; i++) { d_rowptr[i] = run2; run2 += d_deg[i]; }
        d_rowptr[n] = run2;
    }
}

__global__ void scatter_kernel(const int* __restrict__ src, const int* __restrict__ tgt, int E) {
    int e = blockIdx.x * blockDim.x + threadIdx.x;
    if (e < E) {
        int tg = tgt[e];
        int pos = d_rowptr[tg] + atomicAdd(&d_cur[tg], 1);
        d_es[pos] = make_int2(e, src[e]);
    }
}

// ---------------- fp32 tiled GEMM body (R3-measured form, single buffer) ----------------
__device__ __forceinline__ void gemm_body(const float* __restrict__ A,
                                          const float* __restrict__ B,
                                          const float* __restrict__ bias,
                                          float* __restrict__ C, int M, int bm)
{
    __shared__ float As[8][132];
    __shared__ float Bs[8][128];
    int tid = threadIdx.x;
    int tx = tid & 15;
    int ty = tid >> 4;
    int c0 = tx * 8, r0 = ty * 8;
    float acc[8][8];
#pragma unroll
    for (int i = 0; i < 8; i++)
#pragma unroll
        for (int j = 0; j < 8; j++) acc[i][j] = 0.f;

    int a_row = tid >> 1;
    int a_k   = (tid & 1) * 4;
    int b_k   = tid >> 5;
    int b_c   = (tid & 31) * 4;

    for (int k0 = 0; k0 < 128; k0 += 8) {
        int ar = bm + a_row; if (ar >= M) ar = M - 1;
        float4 av = *(const float4*)(A + (size_t)ar * 128 + k0 + a_k);
        As[a_k + 0][a_row] = av.x;
        As[a_k + 1][a_row] = av.y;
        As[a_k + 2][a_row] = av.z;
        As[a_k + 3][a_row] = av.w;
        float4 bv = *(const float4*)(B + (size_t)(k0 + b_k) * 128 + b_c);
        *(float4*)&Bs[b_k][b_c] = bv;
        __syncthreads();
#pragma unroll
        for (int k = 0; k < 8; k++) {
            float4 a0 = *(const float4*)&As[k][r0];
            float4 a1 = *(const float4*)&As[k][r0 + 4];
            float4 b0 = *(const float4*)&Bs[k][c0];
            float4 b1 = *(const float4*)&Bs[k][c0 + 4];
            float aa[8] = {a0.x, a0.y, a0.z, a0.w, a1.x, a1.y, a1.z, a1.w};
            float bb[8] = {b0.x, b0.y, b0.z, b0.w, b1.x, b1.y, b1.z, b1.w};
#pragma unroll
            for (int i = 0; i < 8; i++)
#pragma unroll
                for (int j = 0; j < 8; j++)
                    acc[i][j] += aa[i] * bb[j];
        }
        __syncthreads();
    }
    float4 bias0 = *(const float4*)(bias + c0);
    float4 bias1 = *(const float4*)(bias + c0 + 4);
    float bb[8] = {bias0.x, bias0.y, bias0.z, bias0.w, bias1.x, bias1.y, bias1.z, bias1.w};
#pragma unroll
    for (int i = 0; i < 8; i++) {
        int row = bm + r0 + i;
        if (row < M) {
            float4 o0 = {acc[i][0] + bb[0], acc[i][1] + bb[1], acc[i][2] + bb[2], acc[i][3] + bb[3]};
            float4 o1 = {acc[i][4] + bb[4], acc[i][5] + bb[5], acc[i][6] + bb[6], acc[i][7] + bb[7]};
            *(float4*)(C + (size_t)row * 128 + c0)     = o0;
            *(float4*)(C + (size_t)row * 128 + c0 + 4) = o1;
        }
    }
}

__global__ void __launch_bounds__(256) gemm_k128(const float* __restrict__ A,
                                                 const float* __restrict__ B,
                                                 const float* __restrict__ bias,
                                                 float* __restrict__ C, int M)
{
    gemm_body(A, B, bias, C, M, blockIdx.x * 128);
}

__global__ void __launch_bounds__(256) gemm_qkv(const float* __restrict__ A,
                                                const float* __restrict__ Wq,
                                                const float* __restrict__ bq,
                                                const float* __restrict__ Wk,
                                                const float* __restrict__ bk,
                                                const float* __restrict__ Wv,
                                                const float* __restrict__ bv,
                                                float* __restrict__ Q,
                                                float* __restrict__ K,
                                                float* __restrict__ V, int M)
{
    const float* B;  const float* bias;  float* C;
    if (blockIdx.y == 0)      { B = Wq; bias = bq; C = Q; }
    else if (blockIdx.y == 1) { B = Wk; bias = bk; C = K; }
    else                      { B = Wv; bias = bv; C = V; }
    gemm_body(A, B, bias, C, M, blockIdx.x * 128);
}

// ---------------- fused per-node attention (warp per node, CSR) ----------------
// Lane layout: lane owns channels [4*lane,4*lane+4) -> head h = lane>>2,
// and edge-feature dims [16*(lane&3), +16). Quad (4 lanes) = one head.
// 2 edges per iteration (independent chains, R7 win) + index-pair prefetch:
// the int2 slot records for iteration i+1 load during iteration i, so gather
// addresses are ready at iteration top (removes the L2 index hop from the chain).
__global__ void __launch_bounds__(128) attn_kernel(const float* __restrict__ edge_feats,
                                                   const float* __restrict__ Wk,
                                                   const float* __restrict__ Wv,
                                                   int N)
{
    __shared__ float Wve[64 * 128];   // Wv rows 128..191 (edge part), 32 KB
    int tid = threadIdx.x;
    {
        const float4* s2 = (const float4*)(Wv + 128 * 128);
        float4* dst = (float4*)Wve;
        for (int i = tid; i < 2048; i += blockDim.x) dst[i] = s2[i];
    }
    __syncthreads();

    int lane = tid & 31;
    int warp = tid >> 5;
    int cb = lane * 4;
    int h  = lane >> 2;
    int d0 = (lane & 3) * 16;
    int qb = lane & ~3;

    int gw = blockIdx.x * (blockDim.x >> 5) + warp;
    int nw = gridDim.x * (blockDim.x >> 5);

    for (int n = gw; n < N; n += nw) {
        int beg = d_rowptr[n], end = d_rowptr[n + 1];
        float4 q = *(const float4*)(d_Q + (size_t)n * 128 + cb);

        float qh[16];
#pragma unroll
        for (int t = 0; t < 4; t++) {
            qh[4 * t + 0] = __shfl_sync(FULLMASK, q.x, qb + t);
            qh[4 * t + 1] = __shfl_sync(FULLMASK, q.y, qb + t);
            qh[4 * t + 2] = __shfl_sync(FULLMASK, q.z, qb + t);
            qh[4 * t + 3] = __shfl_sync(FULLMASK, q.w, qb + t);
        }
        float U[16];
#pragma unroll
        for (int j = 0; j < 16; j++) {
            const float4* w = (const float4*)(Wk + (size_t)(128 + d0 + j) * 128 + h * 16);
            float4 w0 = w[0], w1 = w[1], w2 = w[2], w3 = w[3];
            U[j] = qh[0]  * w0.x + qh[1]  * w0.y + qh[2]  * w0.z + qh[3]  * w0.w
                 + qh[4]  * w1.x + qh[5]  * w1.y + qh[6]  * w1.z + qh[7]  * w1.w
                 + qh[8]  * w2.x + qh[9]  * w2.y + qh[10] * w2.z + qh[11] * w2.w
                 + qh[12] * w3.x + qh[13] * w3.y + qh[14] * w3.z + qh[15] * w3.w;
        }

        float g[16];
#pragma unroll
        for (int j = 0; j < 16; j++) g[j] = 0.f;
        float o0 = 0.f, o1 = 0.f, o2 = 0.f, o3 = 0.f, sacc = 0.f;

        int idx = beg;
        int2 esa, esb;
        if (idx + 1 < end) { esa = d_es[idx]; esb = d_es[idx + 1]; }
        // --- pair-unrolled main loop with index prefetch ---
        for (; idx + 1 < end; idx += 2) {
            int2 esa_n, esb_n;
            if (idx + 3 < end) { esa_n = d_es[idx + 2]; esb_n = d_es[idx + 3]; }
            const float4* efa = (const float4*)(edge_feats + (size_t)esa.x * 64 + d0);
            const float4* efb = (const float4*)(edge_feats + (size_t)esb.x * 64 + d0);
            float4 a0 = efa[0], a1 = efa[1], a2 = efa[2], a3 = efa[3];
            float4 b0 = efb[0], b1 = efb[1], b2 = efb[2], b3 = efb[3];
            float4 kna = *(const float4*)(d_Kn + (size_t)esa.y * 128 + cb);
            float4 knb = *(const float4*)(d_Kn + (size_t)esb.y * 128 + cb);
            float4 vna = *(const float4*)(d_Vn + (size_t)esa.y * 128 + cb);
            float4 vnb = *(const float4*)(d_Vn + (size_t)esb.y * 128 + cb);

            float pa = q.x * kna.x + q.y * kna.y + q.z * kna.z + q.w * kna.w;
            float pb = q.x * knb.x + q.y * knb.y + q.z * knb.z + q.w * knb.w;
            pa += a0.x * U[0]  + a0.y * U[1]  + a0.z * U[2]  + a0.w * U[3];
            pb += b0.x * U[0]  + b0.y * U[1]  + b0.z * U[2]  + b0.w * U[3];
            pa += a1.x * U[4]  + a1.y * U[5]  + a1.z * U[6]  + a1.w * U[7];
            pb += b1.x * U[4]  + b1.y * U[5]  + b1.z * U[6]  + b1.w * U[7];
            pa += a2.x * U[8]  + a2.y * U[9]  + a2.z * U[10] + a2.w * U[11];
            pb += b2.x * U[8]  + b2.y * U[9]  + b2.z * U[10] + b2.w * U[11];
            pa += a3.x * U[12] + a3.y * U[13] + a3.z * U[14] + a3.w * U[15];
            pb += b3.x * U[12] + b3.y * U[13] + b3.z * U[14] + b3.w * U[15];
            pa += __shfl_xor_sync(FULLMASK, pa, 1);
            pb += __shfl_xor_sync(FULLMASK, pb, 1);
            pa += __shfl_xor_sync(FULLMASK, pa, 2);
            pb += __shfl_xor_sync(FULLMASK, pb, 2);
            float wa = __expf(0.25f * pa);
            float wb = __expf(0.25f * pb);
            sacc += wa + wb;
            o0 += wa * vna.x + wb * vnb.x;
            o1 += wa * vna.y + wb * vnb.y;
            o2 += wa * vna.z + wb * vnb.z;
            o3 += wa * vna.w + wb * vnb.w;
            g[0]  += wa * a0.x + wb * b0.x; g[1]  += wa * a0.y + wb * b0.y;
            g[2]  += wa * a0.z + wb * b0.z; g[3]  += wa * a0.w + wb * b0.w;
            g[4]  += wa * a1.x + wb * b1.x; g[5]  += wa * a1.y + wb * b1.y;
            g[6]  += wa * a1.z + wb * b1.z; g[7]  += wa * a1.w + wb * b1.w;
            g[8]  += wa * a2.x + wb * b2.x; g[9]  += wa * a2.y + wb * b2.y;
            g[10] += wa * a2.z + wb * b2.z; g[11] += wa * a2.w + wb * b2.w;
            g[12] += wa * a3.x + wb * b3.x; g[13] += wa * a3.y + wb * b3.y;
            g[14] += wa * a3.z + wb * b3.z; g[15] += wa * a3.w + wb * b3.w;
            esa = esa_n; esb = esb_n;
        }
        // --- tail: at most one edge ---
        if (idx < end) {
            int2 es = d_es[idx];
            const float4* ef = (const float4*)(edge_feats + (size_t)es.x * 64 + d0);
            float4 a0 = ef[0], a1 = ef[1], a2 = ef[2], a3 = ef[3];
            float4 kn = *(const float4*)(d_Kn + (size_t)es.y * 128 + cb);
            float4 vn = *(const float4*)(d_Vn + (size_t)es.y * 128 + cb);
            float pa = q.x * kn.x + q.y * kn.y + q.z * kn.z + q.w * kn.w;
            pa += a0.x * U[0]  + a0.y * U[1]  + a0.z * U[2]  + a0.w * U[3];
            pa += a1.x * U[4]  + a1.y * U[5]  + a1.z * U[6]  + a1.w * U[7];
            pa += a2.x * U[8]  + a2.y * U[9]  + a2.z * U[10] + a2.w * U[11];
            pa += a3.x * U[12] + a3.y * U[13] + a3.z * U[14] + a3.w * U[15];
            pa += __shfl_xor_sync(FULLMASK, pa, 1);
            pa += __shfl_xor_sync(FULLMASK, pa, 2);
            float wa = __expf(0.25f * pa);
            sacc += wa;
            o0 += wa * vn.x; o1 += wa * vn.y; o2 += wa * vn.z; o3 += wa * vn.w;
            g[0]  += wa * a0.x; g[1]  += wa * a0.y; g[2]  += wa * a0.z; g[3]  += wa * a0.w;
            g[4]  += wa * a1.x; g[5]  += wa * a1.y; g[6]  += wa * a1.z; g[7]  += wa * a1.w;
            g[8]  += wa * a2.x; g[9]  += wa * a2.y; g[10] += wa * a2.z; g[11] += wa * a2.w;
            g[12] += wa * a3.x; g[13] += wa * a3.y; g[14] += wa * a3.z; g[15] += wa * a3.w;
        }

        // epilogue: o += g @ Wv_e   (g distributed over the quad; exchange via shuffles)
        float ep0 = 0.f, ep1 = 0.f, ep2 = 0.f, ep3 = 0.f;
#pragma unroll
        for (int t = 0; t < 4; t++) {
#pragma unroll
            for (int j = 0; j < 16; j++) {
                float gv = __shfl_sync(FULLMASK, g[j], qb + t);
                float4 w = *(const float4*)(Wve + (size_t)(t * 16 + j) * 128 + cb);
                ep0 += gv * w.x; ep1 += gv * w.y; ep2 += gv * w.z; ep3 += gv * w.w;
            }
        }
        float inv = (sacc > 0.f) ? (1.0f / sacc) : 0.f;
        float4 res;
        res.x = (o0 + ep0) * inv;
        res.y = (o1 + ep1) * inv;
        res.z = (o2 + ep2) * inv;
        res.w = (o3 + ep3) * inv;
        *(float4*)(d_Ov + (size_t)n * 128 + cb) = res;
    }
}

// ---------------- host launcher ----------------
// Launch order puts gemm_qkv at index 3 (the slot ncu captures) to finally
// measure it. d_deg/d_cur are zeroed at the END of each call (and are
// zero-initialized at module load), so deg_kernel can run first.
extern "C" void kernel_launch(void* const* d_in, const int* in_sizes, int n_in,
                              void* d_out, int out_size)
{
    const float* node_feats = (const float*)d_in[0];
    const float* edge_feats = (const float*)d_in[1];
    const int*   edge_index = (const int*)  d_in[2];
    const float* Wq = (const float*)d_in[3];
    const float* bq = (const float*)d_in[4];
    const float* Wk = (const float*)d_in[5];
    const float* bk = (const float*)d_in[6];
    const float* Wv = (const float*)d_in[7];
    const float* bv = (const float*)d_in[8];
    const float* Wo = (const float*)d_in[9];
    const float* bo = (const float*)d_in[10];
    float* out = (float*)d_out;

    int N = in_sizes[0] / 128;
    int E = in_sizes[1] / 64;
    const int* src = edge_index;
    const int* tgt = edge_index + E;

    float *pQ, *pKn, *pVn, *pO;
    cudaGetSymbolAddress((void**)&pQ,  d_Q);
    cudaGetSymbolAddress((void**)&pKn, d_Kn);
    cudaGetSymbolAddress((void**)&pVn, d_Vn);
    cudaGetSymbolAddress((void**)&pO,  d_Ov);

    int gblocks = (N + 127) / 128;

    deg_kernel<<<(E + 255) / 256, 256>>>(tgt, E);                  // idx 0
    scan_kernel<<<1, 1024>>>(N);                                   // idx 1
    scatter_kernel<<<(E + 255) / 256, 256>>>(src, tgt, E);         // idx 2
    gemm_qkv<<<dim3(gblocks, 3), 256>>>(node_feats, Wq, bq, Wk, bk,
                                        Wv, bv, pQ, pKn, pVn, N);  // idx 3 (ncu)
    attn_kernel<<<1776, 128>>>(edge_feats, Wk, Wv, N);             // idx 4
    gemm_k128<<<gblocks, 256>>>(pO, Wo, bo, out, N);               // idx 5
    zero_kernel<<<(N + 255) / 256, 256>>>(N);                      // idx 6: reset for next call
}

// round 9
// speedup vs baseline: 1.1861x; 1.1861x over previous
#include <cuda_runtime.h>

#define NN 50000
#define NE 800000
#define FULLMASK 0xffffffffu

// ---------------- static device scratch (no allocation allowed) ----------------
__device__ float d_Q [NN * 128];
__device__ float d_Kn[NN * 128];
__device__ float d_Vn[NN * 128];
__device__ float d_Ov[NN * 128];
__device__ float d_U [(size_t)NN * 512];   // per-node U: [n][h*64 + d] = [n][lane*16 + j]
__device__ __align__(16) int d_deg[NN];
__device__ int   d_cur[NN];
__device__ __align__(16) int d_rowptr[NN + 4];
__device__ int2  d_es[NE];      // per CSR slot: (edge id, source node)

// ---------------- CSR build ----------------
__global__ void zero_kernel(int n) {
    int i = blockIdx.x * blockDim.x + threadIdx.x;
    if (i < n) { d_deg[i] = 0; d_cur[i] = 0; }
}

__global__ void deg_kernel(const int* __restrict__ tgt, int E) {
    int e = blockIdx.x * blockDim.x + threadIdx.x;
    if (e < E) atomicAdd(&d_deg[tgt[e]], 1);
}

// single-block exclusive scan of d_deg -> d_rowptr, int4-vectorized
__global__ void scan_kernel(int n) {
    __shared__ int ssum[1024];
    int t = threadIdx.x;
    int n4 = n >> 2;
    int C = (n4 + 1023) >> 10;
    int s0 = t * C;
    int s1 = min(s0 + C, n4);
    const int4* deg4 = (const int4*)d_deg;
    int s = 0;
    for (int i = s0; i < s1; i++) {
        int4 v = deg4[i];
        s += v.x + v.y + v.z + v.w;
    }
    ssum[t] = s;
    __syncthreads();
    for (int off = 1; off < 1024; off <<= 1) {
        int v = 0;
        if (t >= off) v = ssum[t - off];
        __syncthreads();
        if (t >= off) ssum[t] += v;
        __syncthreads();
    }
    int run = (t == 0) ? 0 : ssum[t - 1];
    int4* rp4 = (int4*)d_rowptr;
    for (int i = s0; i < s1; i++) {
        int4 v = deg4[i];
        int4 r;
        r.x = run; run += v.x;
        r.y = run; run += v.y;
        r.z = run; run += v.z;
        r.w = run; run += v.w;
        rp4[i] = r;
    }
    if (t == 1023) {
        int run2 = ssum[1023];
        for (int i = n4 * 4; i < n; i++) { d_rowptr[i] = run2; run2 += d_deg[i]; }
        d_rowptr[n] = run2;
    }
}

__global__ void scatter_kernel(const int* __restrict__ src, const int* __restrict__ tgt, int E) {
    int e = blockIdx.x * blockDim.x + threadIdx.x;
    if (e < E) {
        int tg = tgt[e];
        int pos = d_rowptr[tg] + atomicAdd(&d_cur[tg], 1);
        d_es[pos] = make_int2(e, src[e]);
    }
}

// ---------------- fp32 tiled GEMM body ----------------
__device__ __forceinline__ void gemm_body(const float* __restrict__ A,
                                          const float* __restrict__ B,
                                          const float* __restrict__ bias,
                                          float* __restrict__ C, int M, int bm)
{
    __shared__ float As[8][132];
    __shared__ float Bs[8][128];
    int tid = threadIdx.x;
    int tx = tid & 15;
    int ty = tid >> 4;
    int c0 = tx * 8, r0 = ty * 8;
    float acc[8][8];
#pragma unroll
    for (int i = 0; i < 8; i++)
#pragma unroll
        for (int j = 0; j < 8; j++) acc[i][j] = 0.f;

    int a_row = tid >> 1;
    int a_k   = (tid & 1) * 4;
    int b_k   = tid >> 5;
    int b_c   = (tid & 31) * 4;

    for (int k0 = 0; k0 < 128; k0 += 8) {
        int ar = bm + a_row; if (ar >= M) ar = M - 1;
        float4 av = *(const float4*)(A + (size_t)ar * 128 + k0 + a_k);
        As[a_k + 0][a_row] = av.x;
        As[a_k + 1][a_row] = av.y;
        As[a_k + 2][a_row] = av.z;
        As[a_k + 3][a_row] = av.w;
        float4 bv = *(const float4*)(B + (size_t)(k0 + b_k) * 128 + b_c);
        *(float4*)&Bs[b_k][b_c] = bv;
        __syncthreads();
#pragma unroll
        for (int k = 0; k < 8; k++) {
            float4 a0 = *(const float4*)&As[k][r0];
            float4 a1 = *(const float4*)&As[k][r0 + 4];
            float4 b0 = *(const float4*)&Bs[k][c0];
            float4 b1 = *(const float4*)&Bs[k][c0 + 4];
            float aa[8] = {a0.x, a0.y, a0.z, a0.w, a1.x, a1.y, a1.z, a1.w};
            float bb[8] = {b0.x, b0.y, b0.z, b0.w, b1.x, b1.y, b1.z, b1.w};
#pragma unroll
            for (int i = 0; i < 8; i++)
#pragma unroll
                for (int j = 0; j < 8; j++)
                    acc[i][j] += aa[i] * bb[j];
        }
        __syncthreads();
    }
    float4 bias0 = *(const float4*)(bias + c0);
    float4 bias1 = *(const float4*)(bias + c0 + 4);
    float bb[8] = {bias0.x, bias0.y, bias0.z, bias0.w, bias1.x, bias1.y, bias1.z, bias1.w};
#pragma unroll
    for (int i = 0; i < 8; i++) {
        int row = bm + r0 + i;
        if (row < M) {
            float4 o0 = {acc[i][0] + bb[0], acc[i][1] + bb[1], acc[i][2] + bb[2], acc[i][3] + bb[3]};
            float4 o1 = {acc[i][4] + bb[4], acc[i][5] + bb[5], acc[i][6] + bb[6], acc[i][7] + bb[7]};
            *(float4*)(C + (size_t)row * 128 + c0)     = o0;
            *(float4*)(C + (size_t)row * 128 + c0 + 4) = o1;
        }
    }
}

__global__ void __launch_bounds__(256) gemm_k128(const float* __restrict__ A,
                                                 const float* __restrict__ B,
                                                 const float* __restrict__ bias,
                                                 float* __restrict__ C, int M)
{
    gemm_body(A, B, bias, C, M, blockIdx.x * 128);
}

__global__ void __launch_bounds__(256) gemm_qkv(const float* __restrict__ A,
                                                const float* __restrict__ Wq,
                                                const float* __restrict__ bq,
                                                const float* __restrict__ Wk,
                                                const float* __restrict__ bk,
                                                const float* __restrict__ Wv,
                                                const float* __restrict__ bv,
                                                float* __restrict__ Q,
                                                float* __restrict__ K,
                                                float* __restrict__ V, int M)
{
    const float* B;  const float* bias;  float* C;
    if (blockIdx.y == 0)      { B = Wq; bias = bq; C = Q; }
    else if (blockIdx.y == 1) { B = Wk; bias = bk; C = K; }
    else                      { B = Wv; bias = bv; C = V; }
    gemm_body(A, B, bias, C, M, blockIdx.x * 128);
}

// ---------------- U precompute: d_U[n][h*64+d] = sum_c Q[n][16h+c] * Wk[128+d][16h+c] ----
// Wk edge-rows live in padded smem (coalesced global loads once per block);
// per step s: head h = s>>1 fixed across the warp, output d = (s&1)*32 + lane,
// Wks row read is bank-spread (132 pad), q read is broadcast from warp's smem slot.
__global__ void __launch_bounds__(256) u_kernel(const float* __restrict__ Wk, int N)
{
    __shared__ float Wks[64 * 132];          // 33.8 KB
    __shared__ float qsm[8][128];            // 4 KB, one row per warp
    int tid = threadIdx.x;
    // load Wk rows 128..191 (64 x 128) into padded smem
    for (int i = tid; i < 64 * 32; i += blockDim.x) {   // i indexes float4s: 64 rows x 32 f4
        int d = i >> 5;
        int c4 = (i & 31) * 4;
        float4 v = *(const float4*)(Wk + (size_t)(128 + d) * 128 + c4);
        *(float4*)&Wks[d * 132 + c4] = v;
    }
    __syncthreads();

    int lane = tid & 31;
    int w = tid >> 5;
    int gw = blockIdx.x * 8 + w;
    int nw = gridDim.x * 8;

    for (int n = gw; n < N; n += nw) {
        __syncwarp();
        *(float4*)&qsm[w][lane * 4] = *(const float4*)(d_Q + (size_t)n * 128 + lane * 4);
        __syncwarp();
#pragma unroll
        for (int s = 0; s < 16; s++) {
            int h = s >> 1;
            float4 q0 = *(const float4*)&qsm[w][16 * h];
            float4 q1 = *(const float4*)&qsm[w][16 * h + 4];
            float4 q2 = *(const float4*)&qsm[w][16 * h + 8];
            float4 q3 = *(const float4*)&qsm[w][16 * h + 12];
            int d = ((s & 1) << 5) + lane;
            const float* wr = &Wks[d * 132 + 16 * h];
            float4 w0 = *(const float4*)&wr[0];
            float4 w1 = *(const float4*)&wr[4];
            float4 w2 = *(const float4*)&wr[8];
            float4 w3 = *(const float4*)&wr[12];
            float acc = q0.x * w0.x + q0.y * w0.y + q0.z * w0.z + q0.w * w0.w
                      + q1.x * w1.x + q1.y * w1.y + q1.z * w1.z + q1.w * w1.w
                      + q2.x * w2.x + q2.y * w2.y + q2.z * w2.z + q2.w * w2.w
                      + q3.x * w3.x + q3.y * w3.y + q3.z * w3.z + q3.w * w3.w;
            d_U[(size_t)n * 512 + s * 32 + lane] = acc;
        }
    }
}

// ---------------- fused per-node attention (warp per node, CSR) ----------------
// Lane layout: lane owns channels [4*lane,4*lane+4) -> head h = lane>>2,
// and edge-feature dims [16*(lane&3), +16). Quad (4 lanes) = one head.
// Prologue now loads precomputed U: d_U[n*512 + lane*16 + j] (lane-contiguous,
// coalesced) — removes the 1024-wavefront/node Wk gather storm (the R8 finding).
// Edge loop: R7 pair-unrolled form (no index prefetch — R8 showed it regressed).
__global__ void __launch_bounds__(128) attn_kernel(const float* __restrict__ edge_feats,
                                                   const float* __restrict__ Wv,
                                                   int N)
{
    __shared__ float Wve[64 * 128];   // Wv rows 128..191 (edge part), 32 KB
    int tid = threadIdx.x;
    {
        const float4* s2 = (const float4*)(Wv + 128 * 128);
        float4* dst = (float4*)Wve;
        for (int i = tid; i < 2048; i += blockDim.x) dst[i] = s2[i];
    }
    __syncthreads();

    int lane = tid & 31;
    int warp = tid >> 5;
    int cb = lane * 4;
    int d0 = (lane & 3) * 16;
    int qb = lane & ~3;
    (void)d0;

    int gw = blockIdx.x * (blockDim.x >> 5) + warp;
    int nw = gridDim.x * (blockDim.x >> 5);

    for (int n = gw; n < N; n += nw) {
        int beg = d_rowptr[n], end = d_rowptr[n + 1];
        float4 q = *(const float4*)(d_Q + (size_t)n * 128 + cb);

        // coalesced U load: lane-contiguous 64B
        float U[16];
        {
            const float4* Up = (const float4*)(d_U + (size_t)n * 512 + lane * 16);
            float4 u0 = Up[0], u1 = Up[1], u2 = Up[2], u3 = Up[3];
            U[0]=u0.x; U[1]=u0.y; U[2]=u0.z; U[3]=u0.w;
            U[4]=u1.x; U[5]=u1.y; U[6]=u1.z; U[7]=u1.w;
            U[8]=u2.x; U[9]=u2.y; U[10]=u2.z; U[11]=u2.w;
            U[12]=u3.x; U[13]=u3.y; U[14]=u3.z; U[15]=u3.w;
        }

        float g[16];
#pragma unroll
        for (int j = 0; j < 16; j++) g[j] = 0.f;
        float o0 = 0.f, o1 = 0.f, o2 = 0.f, o3 = 0.f, sacc = 0.f;

        int idx = beg;
        int dd0 = (lane & 3) * 16;
        // --- pair-unrolled main loop: 2 independent edges per iteration ---
        for (; idx + 1 < end; idx += 2) {
            int2 esa = d_es[idx];
            int2 esb = d_es[idx + 1];
            const float4* efa = (const float4*)(edge_feats + (size_t)esa.x * 64 + dd0);
            const float4* efb = (const float4*)(edge_feats + (size_t)esb.x * 64 + dd0);
            float4 a0 = efa[0], a1 = efa[1], a2 = efa[2], a3 = efa[3];
            float4 b0 = efb[0], b1 = efb[1], b2 = efb[2], b3 = efb[3];
            float4 kna = *(const float4*)(d_Kn + (size_t)esa.y * 128 + cb);
            float4 knb = *(const float4*)(d_Kn + (size_t)esb.y * 128 + cb);
            float4 vna = *(const float4*)(d_Vn + (size_t)esa.y * 128 + cb);
            float4 vnb = *(const float4*)(d_Vn + (size_t)esb.y * 128 + cb);

            float pa = q.x * kna.x + q.y * kna.y + q.z * kna.z + q.w * kna.w;
            float pb = q.x * knb.x + q.y * knb.y + q.z * knb.z + q.w * knb.w;
            pa += a0.x * U[0]  + a0.y * U[1]  + a0.z * U[2]  + a0.w * U[3];
            pb += b0.x * U[0]  + b0.y * U[1]  + b0.z * U[2]  + b0.w * U[3];
            pa += a1.x * U[4]  + a1.y * U[5]  + a1.z * U[6]  + a1.w * U[7];
            pb += b1.x * U[4]  + b1.y * U[5]  + b1.z * U[6]  + b1.w * U[7];
            pa += a2.x * U[8]  + a2.y * U[9]  + a2.z * U[10] + a2.w * U[11];
            pb += b2.x * U[8]  + b2.y * U[9]  + b2.z * U[10] + b2.w * U[11];
            pa += a3.x * U[12] + a3.y * U[13] + a3.z * U[14] + a3.w * U[15];
            pb += b3.x * U[12] + b3.y * U[13] + b3.z * U[14] + b3.w * U[15];
            pa += __shfl_xor_sync(FULLMASK, pa, 1);
            pb += __shfl_xor_sync(FULLMASK, pb, 1);
            pa += __shfl_xor_sync(FULLMASK, pa, 2);
            pb += __shfl_xor_sync(FULLMASK, pb, 2);
            float wa = __expf(0.25f * pa);
            float wb = __expf(0.25f * pb);
            sacc += wa + wb;
            o0 += wa * vna.x + wb * vnb.x;
            o1 += wa * vna.y + wb * vnb.y;
            o2 += wa * vna.z + wb * vnb.z;
            o3 += wa * vna.w + wb * vnb.w;
            g[0]  += wa * a0.x + wb * b0.x; g[1]  += wa * a0.y + wb * b0.y;
            g[2]  += wa * a0.z + wb * b0.z; g[3]  += wa * a0.w + wb * b0.w;
            g[4]  += wa * a1.x + wb * b1.x; g[5]  += wa * a1.y + wb * b1.y;
            g[6]  += wa * a1.z + wb * b1.z; g[7]  += wa * a1.w + wb * b1.w;
            g[8]  += wa * a2.x + wb * b2.x; g[9]  += wa * a2.y + wb * b2.y;
            g[10] += wa * a2.z + wb * b2.z; g[11] += wa * a2.w + wb * b2.w;
            g[12] += wa * a3.x + wb * b3.x; g[13] += wa * a3.y + wb * b3.y;
            g[14] += wa * a3.z + wb * b3.z; g[15] += wa * a3.w + wb * b3.w;
        }
        // --- tail: at most one edge ---
        if (idx < end) {
            int2 es = d_es[idx];
            const float4* ef = (const float4*)(edge_feats + (size_t)es.x * 64 + dd0);
            float4 a0 = ef[0], a1 = ef[1], a2 = ef[2], a3 = ef[3];
            float4 kn = *(const float4*)(d_Kn + (size_t)es.y * 128 + cb);
            float4 vn = *(const float4*)(d_Vn + (size_t)es.y * 128 + cb);
            float pa = q.x * kn.x + q.y * kn.y + q.z * kn.z + q.w * kn.w;
            pa += a0.x * U[0]  + a0.y * U[1]  + a0.z * U[2]  + a0.w * U[3];
            pa += a1.x * U[4]  + a1.y * U[5]  + a1.z * U[6]  + a1.w * U[7];
            pa += a2.x * U[8]  + a2.y * U[9]  + a2.z * U[10] + a2.w * U[11];
            pa += a3.x * U[12] + a3.y * U[13] + a3.z * U[14] + a3.w * U[15];
            pa += __shfl_xor_sync(FULLMASK, pa, 1);
            pa += __shfl_xor_sync(FULLMASK, pa, 2);
            float wa = __expf(0.25f * pa);
            sacc += wa;
            o0 += wa * vn.x; o1 += wa * vn.y; o2 += wa * vn.z; o3 += wa * vn.w;
            g[0]  += wa * a0.x; g[1]  += wa * a0.y; g[2]  += wa * a0.z; g[3]  += wa * a0.w;
            g[4]  += wa * a1.x; g[5]  += wa * a1.y; g[6]  += wa * a1.z; g[7]  += wa * a1.w;
            g[8]  += wa * a2.x; g[9]  += wa * a2.y; g[10] += wa * a2.z; g[11] += wa * a2.w;
            g[12] += wa * a3.x; g[13] += wa * a3.y; g[14] += wa * a3.z; g[15] += wa * a3.w;
        }

        // epilogue: o += g @ Wv_e   (g distributed over the quad; exchange via shuffles)
        float ep0 = 0.f, ep1 = 0.f, ep2 = 0.f, ep3 = 0.f;
#pragma unroll
        for (int t = 0; t < 4; t++) {
#pragma unroll
            for (int j = 0; j < 16; j++) {
                float gv = __shfl_sync(FULLMASK, g[j], qb + t);
                float4 w = *(const float4*)(Wve + (size_t)(t * 16 + j) * 128 + cb);
                ep0 += gv * w.x; ep1 += gv * w.y; ep2 += gv * w.z; ep3 += gv * w.w;
            }
        }
        float inv = (sacc > 0.f) ? (1.0f / sacc) : 0.f;
        float4 res;
        res.x = (o0 + ep0) * inv;
        res.y = (o1 + ep1) * inv;
        res.z = (o2 + ep2) * inv;
        res.w = (o3 + ep3) * inv;
        *(float4*)(d_Ov + (size_t)n * 128 + cb) = res;
    }
}

// ---------------- host launcher ----------------
extern "C" void kernel_launch(void* const* d_in, const int* in_sizes, int n_in,
                              void* d_out, int out_size)
{
    const float* node_feats = (const float*)d_in[0];
    const float* edge_feats = (const float*)d_in[1];
    const int*   edge_index = (const int*)  d_in[2];
    const float* Wq = (const float*)d_in[3];
    const float* bq = (const float*)d_in[4];
    const float* Wk = (const float*)d_in[5];
    const float* bk = (const float*)d_in[6];
    const float* Wv = (const float*)d_in[7];
    const float* bv = (const float*)d_in[8];
    const float* Wo = (const float*)d_in[9];
    const float* bo = (const float*)d_in[10];
    float* out = (float*)d_out;

    int N = in_sizes[0] / 128;
    int E = in_sizes[1] / 64;
    const int* src = edge_index;
    const int* tgt = edge_index + E;

    float *pQ, *pKn, *pVn, *pO;
    cudaGetSymbolAddress((void**)&pQ,  d_Q);
    cudaGetSymbolAddress((void**)&pKn, d_Kn);
    cudaGetSymbolAddress((void**)&pVn, d_Vn);
    cudaGetSymbolAddress((void**)&pO,  d_Ov);

    int gblocks = (N + 127) / 128;

    deg_kernel<<<(E + 255) / 256, 256>>>(tgt, E);                  // idx 0
    scan_kernel<<<1, 1024>>>(N);                                   // idx 1
    scatter_kernel<<<(E + 255) / 256, 256>>>(src, tgt, E);         // idx 2
    gemm_qkv<<<dim3(gblocks, 3), 256>>>(node_feats, Wq, bq, Wk, bk,
                                        Wv, bv, pQ, pKn, pVn, N);  // idx 3 (ncu slot)
    u_kernel<<<592, 256>>>(Wk, N);                                 // idx 4
    attn_kernel<<<1776, 128>>>(edge_feats, Wv, N);                 // idx 5
    gemm_k128<<<gblocks, 256>>>(pO, Wo, bo, out, N);               // idx 6
    zero_kernel<<<(N + 255) / 256, 256>>>(N);                      // idx 7: reset for next call
}

// round 11
// speedup vs baseline: 1.2341x; 1.0404x over previous
#include <cuda_runtime.h>

#define NN 50000
#define NE 800000
#define FULLMASK 0xffffffffu

// ---------------- static device scratch (no allocation allowed) ----------------
__device__ float d_Q [NN * 128];
__device__ float d_Kn[NN * 128];
__device__ float d_Vn[NN * 128];
__device__ float d_Ov[NN * 128];
__device__ float d_U [(size_t)NN * 512];   // per-node U: [n][h*64 + d]
__device__ __align__(16) int d_deg[NN];
__device__ int   d_cur[NN];
__device__ __align__(16) int d_rowptr[NN + 4];
__device__ int2  d_es[NE];      // per CSR slot: (edge id, source node)

// ---------------- CSR build ----------------
__global__ void zero_kernel(int n) {
    int i = blockIdx.x * blockDim.x + threadIdx.x;
    if (i < n) { d_deg[i] = 0; d_cur[i] = 0; }
}

__global__ void deg_kernel(const int* __restrict__ tgt, int E) {
    int e = blockIdx.x * blockDim.x + threadIdx.x;
    if (e < E) atomicAdd(&d_deg[tgt[e]], 1);
}

// single-block exclusive scan of d_deg -> d_rowptr, int4-vectorized
__global__ void scan_kernel(int n) {
    __shared__ int ssum[1024];
    int t = threadIdx.x;
    int n4 = n >> 2;
    int C = (n4 + 1023) >> 10;
    int s0 = t * C;
    int s1 = min(s0 + C, n4);
    const int4* deg4 = (const int4*)d_deg;
    int s = 0;
    for (int i = s0; i < s1; i++) {
        int4 v = deg4[i];
        s += v.x + v.y + v.z + v.w;
    }
    ssum[t] = s;
    __syncthreads();
    for (int off = 1; off < 1024; off <<= 1) {
        int v = 0;
        if (t >= off) v = ssum[t - off];
        __syncthreads();
        if (t >= off) ssum[t] += v;
        __syncthreads();
    }
    int run = (t == 0) ? 0 : ssum[t - 1];
    int4* rp4 = (int4*)d_rowptr;
    for (int i = s0; i < s1; i++) {
        int4 v = deg4[i];
        int4 r;
        r.x = run; run += v.x;
        r.y = run; run += v.y;
        r.z = run; run += v.z;
        r.w = run; run += v.w;
        rp4[i] = r;
    }
    if (t == 1023) {
        int run2 = ssum[1023];
        for (int i = n4 * 4; i < n; i++) { d_rowptr[i] = run2; run2 += d_deg[i]; }
        d_rowptr[n] = run2;
    }
}

__global__ void scatter_kernel(const int* __restrict__ src, const int* __restrict__ tgt, int E) {
    int e = blockIdx.x * blockDim.x + threadIdx.x;
    if (e < E) {
        int tg = tgt[e];
        int pos = d_rowptr[tg] + atomicAdd(&d_cur[tg], 1);
        d_es[pos] = make_int2(e, src[e]);
    }
}

// ---------------- fp32 tiled GEMM body ----------------
__device__ __forceinline__ void gemm_body(const float* __restrict__ A,
                                          const float* __restrict__ B,
                                          const float* __restrict__ bias,
                                          float* __restrict__ C, int M, int bm)
{
    __shared__ float As[8][132];
    __shared__ float Bs[8][128];
    int tid = threadIdx.x;
    int tx = tid & 15;
    int ty = tid >> 4;
    int c0 = tx * 8, r0 = ty * 8;
    float acc[8][8];
#pragma unroll
    for (int i = 0; i < 8; i++)
#pragma unroll
        for (int j = 0; j < 8; j++) acc[i][j] = 0.f;

    int a_row = tid >> 1;
    int a_k   = (tid & 1) * 4;
    int b_k   = tid >> 5;
    int b_c   = (tid & 31) * 4;

    for (int k0 = 0; k0 < 128; k0 += 8) {
        int ar = bm + a_row; if (ar >= M) ar = M - 1;
        float4 av = *(const float4*)(A + (size_t)ar * 128 + k0 + a_k);
        As[a_k + 0][a_row] = av.x;
        As[a_k + 1][a_row] = av.y;
        As[a_k + 2][a_row] = av.z;
        As[a_k + 3][a_row] = av.w;
        float4 bv = *(const float4*)(B + (size_t)(k0 + b_k) * 128 + b_c);
        *(float4*)&Bs[b_k][b_c] = bv;
        __syncthreads();
#pragma unroll
        for (int k = 0; k < 8; k++) {
            float4 a0 = *(const float4*)&As[k][r0];
            float4 a1 = *(const float4*)&As[k][r0 + 4];
            float4 b0 = *(const float4*)&Bs[k][c0];
            float4 b1 = *(const float4*)&Bs[k][c0 + 4];
            float aa[8] = {a0.x, a0.y, a0.z, a0.w, a1.x, a1.y, a1.z, a1.w};
            float bb[8] = {b0.x, b0.y, b0.z, b0.w, b1.x, b1.y, b1.z, b1.w};
#pragma unroll
            for (int i = 0; i < 8; i++)
#pragma unroll
                for (int j = 0; j < 8; j++)
                    acc[i][j] += aa[i] * bb[j];
        }
        __syncthreads();
    }
    float4 bias0 = *(const float4*)(bias + c0);
    float4 bias1 = *(const float4*)(bias + c0 + 4);
    float bb[8] = {bias0.x, bias0.y, bias0.z, bias0.w, bias1.x, bias1.y, bias1.z, bias1.w};
#pragma unroll
    for (int i = 0; i < 8; i++) {
        int row = bm + r0 + i;
        if (row < M) {
            float4 o0 = {acc[i][0] + bb[0], acc[i][1] + bb[1], acc[i][2] + bb[2], acc[i][3] + bb[3]};
            float4 o1 = {acc[i][4] + bb[4], acc[i][5] + bb[5], acc[i][6] + bb[6], acc[i][7] + bb[7]};
            *(float4*)(C + (size_t)row * 128 + c0)     = o0;
            *(float4*)(C + (size_t)row * 128 + c0 + 4) = o1;
        }
    }
}

__global__ void __launch_bounds__(256) gemm_k128(const float* __restrict__ A,
                                                 const float* __restrict__ B,
                                                 const float* __restrict__ bias,
                                                 float* __restrict__ C, int M)
{
    gemm_body(A, B, bias, C, M, blockIdx.x * 128);
}

__global__ void __launch_bounds__(256) gemm_qkv(const float* __restrict__ A,
                                                const float* __restrict__ Wq,
                                                const float* __restrict__ bq,
                                                const float* __restrict__ Wk,
                                                const float* __restrict__ bk,
                                                const float* __restrict__ Wv,
                                                const float* __restrict__ bv,
                                                float* __restrict__ Q,
                                                float* __restrict__ K,
                                                float* __restrict__ V, int M)
{
    const float* B;  const float* bias;  float* C;
    if (blockIdx.y == 0)      { B = Wq; bias = bq; C = Q; }
    else if (blockIdx.y == 1) { B = Wk; bias = bk; C = K; }
    else                      { B = Wv; bias = bv; C = V; }
    gemm_body(A, B, bias, C, M, blockIdx.x * 128);
}

// ---------------- U precompute: d_U[n][h*64+d] = sum_c Q[n][16h+c] * Wk[128+d][16h+c] ----
__global__ void __launch_bounds__(256) u_kernel(const float* __restrict__ Wk, int N)
{
    __shared__ float Wks[64 * 132];          // 33.8 KB
    __shared__ float qsm[8][128];            // 4 KB, one row per warp
    int tid = threadIdx.x;
    for (int i = tid; i < 64 * 32; i += blockDim.x) {   // i indexes float4s
        int d = i >> 5;
        int c4 = (i & 31) * 4;
        float4 v = *(const float4*)(Wk + (size_t)(128 + d) * 128 + c4);
        *(float4*)&Wks[d * 132 + c4] = v;
    }
    __syncthreads();

    int lane = tid & 31;
    int w = tid >> 5;
    int gw = blockIdx.x * 8 + w;
    int nw = gridDim.x * 8;

    for (int n = gw; n < N; n += nw) {
        __syncwarp();
        *(float4*)&qsm[w][lane * 4] = *(const float4*)(d_Q + (size_t)n * 128 + lane * 4);
        __syncwarp();
#pragma unroll
        for (int s = 0; s < 16; s++) {
            int h = s >> 1;
            float4 q0 = *(const float4*)&qsm[w][16 * h];
            float4 q1 = *(const float4*)&qsm[w][16 * h + 4];
            float4 q2 = *(const float4*)&qsm[w][16 * h + 8];
            float4 q3 = *(const float4*)&qsm[w][16 * h + 12];
            int d = ((s & 1) << 5) + lane;
            const float* wr = &Wks[d * 132 + 16 * h];
            float4 w0 = *(const float4*)&wr[0];
            float4 w1 = *(const float4*)&wr[4];
            float4 w2 = *(const float4*)&wr[8];
            float4 w3 = *(const float4*)&wr[12];
            float acc = q0.x * w0.x + q0.y * w0.y + q0.z * w0.z + q0.w * w0.w
                      + q1.x * w1.x + q1.y * w1.y + q1.z * w1.z + q1.w * w1.w
                      + q2.x * w2.x + q2.y * w2.y + q2.z * w2.z + q2.w * w2.w
                      + q3.x * w3.x + q3.y * w3.y + q3.z * w3.z + q3.w * w3.w;
            d_U[(size_t)n * 512 + s * 32 + lane] = acc;   // layout == n*512 + h*64 + d
        }
    }
}

// ---------------- fused attention: 2 warps per node, 4 heads per warp ----------------
// Warp handles heads [W*4, W*4+4). 8 lanes per head: lane owns 2 channels
// (c = h*16 + 2*(lane&7)) and 8 ef dims (d = 8*(lane&7)). Logit reduced over the
// 8-lane head group (xor 1,2,4). ~60 live regs -> 8 blocks/SM = 32 warps/SM,
// pair-unrolled = 64 chains in flight (vs 40 in R9). Warp pair of a node shares
// a block so its duplicated es/ef loads hit L1. No smem: epilogue reads the
// L1-resident Wv edge slice directly.
__global__ void __launch_bounds__(128) attn_kernel(const float* __restrict__ edge_feats,
                                                   const float* __restrict__ Wv,
                                                   int N)
{
    int tid  = threadIdx.x;
    int lane = tid & 31;
    int wid  = tid >> 5;
    int le   = lane & 7;          // lane within head group
    int hh   = lane >> 3;         // head within half (0..3)
    int base = lane & 24;         // first lane of this head group

    int gj = blockIdx.x * 4 + wid;
    int NJ = 2 * N;
    int nw = gridDim.x * 4;

    for (int job = gj; job < NJ; job += nw) {
        int n = job >> 1;
        int W = job & 1;
        int h  = W * 4 + hh;              // global head
        int cb = h * 16 + le * 2;         // 2 owned channels
        int d0 = le * 8;                  // 8 owned ef dims

        int beg = d_rowptr[n], end = d_rowptr[n + 1];

        float2 q = *(const float2*)(d_Q + (size_t)n * 128 + cb);
        const float4* Up = (const float4*)(d_U + (size_t)n * 512 + h * 64 + d0);
        float4 u0 = Up[0], u1 = Up[1];
        float U[8] = {u0.x, u0.y, u0.z, u0.w, u1.x, u1.y, u1.z, u1.w};

        float g[8] = {0.f, 0.f, 0.f, 0.f, 0.f, 0.f, 0.f, 0.f};
        float oo0 = 0.f, oo1 = 0.f, sacc = 0.f;

        int idx = beg;
        // --- pair-unrolled main loop: 2 independent edges per iteration ---
        for (; idx + 1 < end; idx += 2) {
            int2 esa = d_es[idx];
            int2 esb = d_es[idx + 1];
            const float4* efa = (const float4*)(edge_feats + (size_t)esa.x * 64 + d0);
            const float4* efb = (const float4*)(edge_feats + (size_t)esb.x * 64 + d0);
            float4 a0 = efa[0], a1 = efa[1];
            float4 b0 = efb[0], b1 = efb[1];
            float2 kna = *(const float2*)(d_Kn + (size_t)esa.y * 128 + cb);
            float2 knb = *(const float2*)(d_Kn + (size_t)esb.y * 128 + cb);
            float2 vna = *(const float2*)(d_Vn + (size_t)esa.y * 128 + cb);
            float2 vnb = *(const float2*)(d_Vn + (size_t)esb.y * 128 + cb);

            float pa = q.x * kna.x + q.y * kna.y
                     + a0.x * U[0] + a0.y * U[1] + a0.z * U[2] + a0.w * U[3]
                     + a1.x * U[4] + a1.y * U[5] + a1.z * U[6] + a1.w * U[7];
            float pb = q.x * knb.x + q.y * knb.y
                     + b0.x * U[0] + b0.y * U[1] + b0.z * U[2] + b0.w * U[3]
                     + b1.x * U[4] + b1.y * U[5] + b1.z * U[6] + b1.w * U[7];
            pa += __shfl_xor_sync(FULLMASK, pa, 1);
            pb += __shfl_xor_sync(FULLMASK, pb, 1);
            pa += __shfl_xor_sync(FULLMASK, pa, 2);
            pb += __shfl_xor_sync(FULLMASK, pb, 2);
            pa += __shfl_xor_sync(FULLMASK, pa, 4);
            pb += __shfl_xor_sync(FULLMASK, pb, 4);
            float wa = __expf(0.25f * pa);
            float wb = __expf(0.25f * pb);
            sacc += wa + wb;
            oo0 += wa * vna.x + wb * vnb.x;
            oo1 += wa * vna.y + wb * vnb.y;
            g[0] += wa * a0.x + wb * b0.x;
            g[1] += wa * a0.y + wb * b0.y;
            g[2] += wa * a0.z + wb * b0.z;
            g[3] += wa * a0.w + wb * b0.w;
            g[4] += wa * a1.x + wb * b1.x;
            g[5] += wa * a1.y + wb * b1.y;
            g[6] += wa * a1.z + wb * b1.z;
            g[7] += wa * a1.w + wb * b1.w;
        }
        // --- tail: at most one edge ---
        if (idx < end) {
            int2 es = d_es[idx];
            const float4* ef = (const float4*)(edge_feats + (size_t)es.x * 64 + d0);
            float4 a0 = ef[0], a1 = ef[1];
            float2 kn = *(const float2*)(d_Kn + (size_t)es.y * 128 + cb);
            float2 vn = *(const float2*)(d_Vn + (size_t)es.y * 128 + cb);
            float pa = q.x * kn.x + q.y * kn.y
                     + a0.x * U[0] + a0.y * U[1] + a0.z * U[2] + a0.w * U[3]
                     + a1.x * U[4] + a1.y * U[5] + a1.z * U[6] + a1.w * U[7];
            pa += __shfl_xor_sync(FULLMASK, pa, 1);
            pa += __shfl_xor_sync(FULLMASK, pa, 2);
            pa += __shfl_xor_sync(FULLMASK, pa, 4);
            float wa = __expf(0.25f * pa);
            sacc += wa;
            oo0 += wa * vn.x;
            oo1 += wa * vn.y;
            g[0] += wa * a0.x; g[1] += wa * a0.y; g[2] += wa * a0.z; g[3] += wa * a0.w;
            g[4] += wa * a1.x; g[5] += wa * a1.y; g[6] += wa * a1.z; g[7] += wa * a1.w;
        }

        // epilogue: o_c += sum_d g_head[d] * Wv_e[d][c]; g_head gathered from the
        // 8-lane group via shuffles. Wv edge slice (32 KB) is L1-resident.
        float ep0 = 0.f, ep1 = 0.f;
#pragma unroll
        for (int t = 0; t < 8; t++) {
#pragma unroll
            for (int j = 0; j < 8; j++) {
                float gv = __shfl_sync(FULLMASK, g[j], base + t);
                float2 w = *(const float2*)(Wv + (size_t)(128 + t * 8 + j) * 128 + cb);
                ep0 += gv * w.x;
                ep1 += gv * w.y;
            }
        }
        float inv = (sacc > 0.f) ? (1.0f / sacc) : 0.f;
        float2 res;
        res.x = (oo0 + ep0) * inv;
        res.y = (oo1 + ep1) * inv;
        *(float2*)(d_Ov + (size_t)n * 128 + cb) = res;
    }
}

// ---------------- host launcher ----------------
extern "C" void kernel_launch(void* const* d_in, const int* in_sizes, int n_in,
                              void* d_out, int out_size)
{
    const float* node_feats = (const float*)d_in[0];
    const float* edge_feats = (const float*)d_in[1];
    const int*   edge_index = (const int*)  d_in[2];
    const float* Wq = (const float*)d_in[3];
    const float* bq = (const float*)d_in[4];
    const float* Wk = (const float*)d_in[5];
    const float* bk = (const float*)d_in[6];
    const float* Wv = (const float*)d_in[7];
    const float* bv = (const float*)d_in[8];
    const float* Wo = (const float*)d_in[9];
    const float* bo = (const float*)d_in[10];
    float* out = (float*)d_out;

    int N = in_sizes[0] / 128;
    int E = in_sizes[1] / 64;
    const int* src = edge_index;
    const int* tgt = edge_index + E;

    float *pQ, *pKn, *pVn, *pO;
    cudaGetSymbolAddress((void**)&pQ,  d_Q);
    cudaGetSymbolAddress((void**)&pKn, d_Kn);
    cudaGetSymbolAddress((void**)&pVn, d_Vn);
    cudaGetSymbolAddress((void**)&pO,  d_Ov);

    int gblocks = (N + 127) / 128;
    int ablocks = (2 * N + 3) / 4;   // 2 warp-jobs per node, 4 warps per block

    deg_kernel<<<(E + 255) / 256, 256>>>(tgt, E);                  // idx 0
    scan_kernel<<<1, 1024>>>(N);                                   // idx 1
    scatter_kernel<<<(E + 255) / 256, 256>>>(src, tgt, E);         // idx 2
    gemm_qkv<<<dim3(gblocks, 3), 256>>>(node_feats, Wq, bq, Wk, bk,
                                        Wv, bv, pQ, pKn, pVn, N);  // idx 3 (ncu slot)
    u_kernel<<<592, 256>>>(Wk, N);                                 // idx 4
    attn_kernel<<<ablocks, 128>>>(edge_feats, Wv, N);              // idx 5
    gemm_k128<<<gblocks, 256>>>(pO, Wo, bo, out, N);               // idx 6
    zero_kernel<<<(N + 255) / 256, 256>>>(N);                      // idx 7: reset for next call
}

// round 15
// speedup vs baseline: 1.3185x; 1.0684x over previous
#include <cuda_runtime.h>
#include <cuda_bf16.h>
#include <cstdint>

#define NN 50000
#define NE 800000
#define FULLMASK 0xffffffffu

// ---------------- static device scratch (no allocation allowed) ----------------
__device__ float d_Q [NN * 128];
__device__ float d_Kn[NN * 128];
__device__ float d_Vn[NN * 128];
__device__ float d_Ov[NN * 128];
__device__ float d_U [(size_t)NN * 512];   // per-node U: [n][h*64 + d]
__device__ __align__(16) int d_deg[NN];
__device__ int   d_cur[NN];
__device__ __align__(16) int d_rowptr[NN + 4];
__device__ int2  d_es[NE];      // per CSR slot: (edge id, source node)

// ---------------- CSR build ----------------
__global__ void zero_kernel(int n) {
    int i = blockIdx.x * blockDim.x + threadIdx.x;
    if (i < n) { d_deg[i] = 0; d_cur[i] = 0; }
}

__global__ void deg_kernel(const int* __restrict__ tgt, int E) {
    int e = blockIdx.x * blockDim.x + threadIdx.x;
    if (e < E) atomicAdd(&d_deg[tgt[e]], 1);
}

// single-block exclusive scan of d_deg -> d_rowptr, int4-vectorized
__global__ void scan_kernel(int n) {
    __shared__ int ssum[1024];
    int t = threadIdx.x;
    int n4 = n >> 2;
    int C = (n4 + 1023) >> 10;
    int s0 = t * C;
    int s1 = min(s0 + C, n4);
    const int4* deg4 = (const int4*)d_deg;
    int s = 0;
    for (int i = s0; i < s1; i++) {
        int4 v = deg4[i];
        s += v.x + v.y + v.z + v.w;
    }
    ssum[t] = s;
    __syncthreads();
    for (int off = 1; off < 1024; off <<= 1) {
        int v = 0;
        if (t >= off) v = ssum[t - off];
        __syncthreads();
        if (t >= off) ssum[t] += v;
        __syncthreads();
    }
    int run = (t == 0) ? 0 : ssum[t - 1];
    int4* rp4 = (int4*)d_rowptr;
    for (int i = s0; i < s1; i++) {
        int4 v = deg4[i];
        int4 r;
        r.x = run; run += v.x;
        r.y = run; run += v.y;
        r.z = run; run += v.z;
        r.w = run; run += v.w;
        rp4[i] = r;
    }
    if (t == 1023) {
        int run2 = ssum[1023];
        for (int i = n4 * 4; i < n; i++) { d_rowptr[i] = run2; run2 += d_deg[i]; }
        d_rowptr[n] = run2;
    }
}

__global__ void scatter_kernel(const int* __restrict__ src, const int* __restrict__ tgt, int E) {
    int e = blockIdx.x * blockDim.x + threadIdx.x;
    if (e < E) {
        int tg = tgt[e];
        int pos = d_rowptr[tg] + atomicAdd(&d_cur[tg], 1);
        d_es[pos] = make_int2(e, src[e]);
    }
}

// ---------------- bf16 split-3 tensor-core GEMM ----------------
// C[M,128] = A[M,128] @ B[128,128] + bias, fp32 in/out.
// a = hi + lo (bf16 each); C accumulates hi*hi + lo*hi + hi*lo in fp32 mma.
// Dropped lo*lo term ~2^-18 relative -> output rel err ~5e-5.
__device__ __forceinline__ void mma_bf16(float* c, const uint32_t* a, uint32_t b0, uint32_t b1) {
    asm volatile(
        "mma.sync.aligned.m16n8k16.row.col.f32.bf16.bf16.f32 "
        "{%0,%1,%2,%3}, {%4,%5,%6,%7}, {%8,%9}, {%0,%1,%2,%3};\n"
        : "+f"(c[0]), "+f"(c[1]), "+f"(c[2]), "+f"(c[3])
        : "r"(a[0]), "r"(a[1]), "r"(a[2]), "r"(a[3]), "r"(b0), "r"(b1));
}

#define SMS 40   // smem row stride (bf16 elems): bank-conflict-free fragment loads

__device__ __forceinline__ void gemm_tc_body(const float* __restrict__ A,
                                             const float* __restrict__ B,
                                             const float* __restrict__ bias,
                                             float* __restrict__ C, int M, int bm)
{
    __shared__ __nv_bfloat16 Ah[128][SMS], Al[128][SMS];
    __shared__ __nv_bfloat16 Bh[128][SMS], Bl[128][SMS];   // transposed: [n][k]

    int tid  = threadIdx.x;
    int lane = tid & 31;
    int wid  = tid >> 5;
    int wm = (wid & 3) * 32;      // warp m-offset
    int wn = (wid >> 2) * 64;     // warp n-offset
    int g  = lane >> 2;           // groupID
    int tg = lane & 3;            // thread-in-group

    float acc[2][8][4];
#pragma unroll
    for (int mi = 0; mi < 2; mi++)
#pragma unroll
        for (int ni = 0; ni < 8; ni++)
#pragma unroll
            for (int c = 0; c < 4; c++) acc[mi][ni][c] = 0.f;

    for (int k0 = 0; k0 < 128; k0 += 32) {
        // stage A chunk [128][32] as bf16 hi/lo
        {
            int r  = tid >> 1;
            int cs = (tid & 1) * 16;
            int ar = bm + r; if (ar >= M) ar = M - 1;
            const float4* ap = (const float4*)(A + (size_t)ar * 128 + k0 + cs);
#pragma unroll
            for (int i = 0; i < 4; i++) {
                float4 v = ap[i];
                float vv[4] = {v.x, v.y, v.z, v.w};
#pragma unroll
                for (int j = 0; j < 4; j++) {
                    __nv_bfloat16 h = __float2bfloat16_rn(vv[j]);
                    Ah[r][cs + 4 * i + j] = h;
                    Al[r][cs + 4 * i + j] = __float2bfloat16_rn(vv[j] - __bfloat162float(h));
                }
            }
        }
        // stage B chunk [32][128] transposed -> [n][k] bf16 hi/lo
        {
            int kk = tid >> 3;             // 0..31
            int ns = (tid & 7) * 16;
            const float4* bp = (const float4*)(B + (size_t)(k0 + kk) * 128 + ns);
#pragma unroll
            for (int i = 0; i < 4; i++) {
                float4 v = bp[i];
                float vv[4] = {v.x, v.y, v.z, v.w};
#pragma unroll
                for (int j = 0; j < 4; j++) {
                    __nv_bfloat16 h = __float2bfloat16_rn(vv[j]);
                    Bh[ns + 4 * i + j][kk] = h;
                    Bl[ns + 4 * i + j][kk] = __float2bfloat16_rn(vv[j] - __bfloat162float(h));
                }
            }
        }
        __syncthreads();

#pragma unroll
        for (int s = 0; s < 32; s += 16) {
            uint32_t ah[2][4], al[2][4];
#pragma unroll
            for (int mi = 0; mi < 2; mi++) {
                int r0 = wm + mi * 16;
                ah[mi][0] = *(const uint32_t*)&Ah[r0 + g    ][s + 2 * tg];
                ah[mi][1] = *(const uint32_t*)&Ah[r0 + g + 8][s + 2 * tg];
                ah[mi][2] = *(const uint32_t*)&Ah[r0 + g    ][s + 2 * tg + 8];
                ah[mi][3] = *(const uint32_t*)&Ah[r0 + g + 8][s + 2 * tg + 8];
                al[mi][0] = *(const uint32_t*)&Al[r0 + g    ][s + 2 * tg];
                al[mi][1] = *(const uint32_t*)&Al[r0 + g + 8][s + 2 * tg];
                al[mi][2] = *(const uint32_t*)&Al[r0 + g    ][s + 2 * tg + 8];
                al[mi][3] = *(const uint32_t*)&Al[r0 + g + 8][s + 2 * tg + 8];
            }
#pragma unroll
            for (int ni = 0; ni < 8; ni++) {
                int n0 = wn + ni * 8 + g;
                uint32_t bh0 = *(const uint32_t*)&Bh[n0][s + 2 * tg];
                uint32_t bh1 = *(const uint32_t*)&Bh[n0][s + 2 * tg + 8];
                uint32_t bl0 = *(const uint32_t*)&Bl[n0][s + 2 * tg];
                uint32_t bl1 = *(const uint32_t*)&Bl[n0][s + 2 * tg + 8];
#pragma unroll
                for (int mi = 0; mi < 2; mi++) {
                    mma_bf16(acc[mi][ni], ah[mi], bh0, bh1);   // hi*hi
                    mma_bf16(acc[mi][ni], al[mi], bh0, bh1);   // lo*hi
                    mma_bf16(acc[mi][ni], ah[mi], bl0, bl1);   // hi*lo
                }
            }
        }
        __syncthreads();
    }

    // epilogue: c0,c1 -> (row g, cols 2tg,2tg+1); c2,c3 -> row g+8
#pragma unroll
    for (int mi = 0; mi < 2; mi++) {
        int r0 = bm + wm + mi * 16 + g;
#pragma unroll
        for (int ni = 0; ni < 8; ni++) {
            int col = wn + ni * 8 + 2 * tg;
            float2 bs = *(const float2*)(bias + col);
            if (r0 < M) {
                float2 v = {acc[mi][ni][0] + bs.x, acc[mi][ni][1] + bs.y};
                *(float2*)(C + (size_t)r0 * 128 + col) = v;
            }
            if (r0 + 8 < M) {
                float2 v = {acc[mi][ni][2] + bs.x, acc[mi][ni][3] + bs.y};
                *(float2*)(C + (size_t)(r0 + 8) * 128 + col) = v;
            }
        }
    }
}

__global__ void __launch_bounds__(256) gemm_k128(const float* __restrict__ A,
                                                 const float* __restrict__ B,
                                                 const float* __restrict__ bias,
                                                 float* __restrict__ C, int M)
{
    gemm_tc_body(A, B, bias, C, M, blockIdx.x * 128);
}

__global__ void __launch_bounds__(256) gemm_qkv(const float* __restrict__ A,
                                                const float* __restrict__ Wq,
                                                const float* __restrict__ bq,
                                                const float* __restrict__ Wk,
                                                const float* __restrict__ bk,
                                                const float* __restrict__ Wv,
                                                const float* __restrict__ bv,
                                                float* __restrict__ Q,
                                                float* __restrict__ K,
                                                float* __restrict__ V, int M)
{
    const float* B;  const float* bias;  float* C;
    if (blockIdx.y == 0)      { B = Wq; bias = bq; C = Q; }
    else if (blockIdx.y == 1) { B = Wk; bias = bk; C = K; }
    else                      { B = Wv; bias = bv; C = V; }
    gemm_tc_body(A, B, bias, C, M, blockIdx.x * 128);
}

// ---------------- U precompute: d_U[n][h*64+d] = sum_c Q[n][16h+c] * Wk[128+d][16h+c] ----
__global__ void __launch_bounds__(256) u_kernel(const float* __restrict__ Wk, int N)
{
    __shared__ float Wks[64 * 132];          // 33.8 KB
    __shared__ float qsm[8][128];            // 4 KB, one row per warp
    int tid = threadIdx.x;
    for (int i = tid; i < 64 * 32; i += blockDim.x) {   // i indexes float4s
        int d = i >> 5;
        int c4 = (i & 31) * 4;
        float4 v = *(const float4*)(Wk + (size_t)(128 + d) * 128 + c4);
        *(float4*)&Wks[d * 132 + c4] = v;
    }
    __syncthreads();

    int lane = tid & 31;
    int w = tid >> 5;
    int gw = blockIdx.x * 8 + w;
    int nw = gridDim.x * 8;

    for (int n = gw; n < N; n += nw) {
        __syncwarp();
        *(float4*)&qsm[w][lane * 4] = *(const float4*)(d_Q + (size_t)n * 128 + lane * 4);
        __syncwarp();
#pragma unroll
        for (int s = 0; s < 16; s++) {
            int h = s >> 1;
            float4 q0 = *(const float4*)&qsm[w][16 * h];
            float4 q1 = *(const float4*)&qsm[w][16 * h + 4];
            float4 q2 = *(const float4*)&qsm[w][16 * h + 8];
            float4 q3 = *(const float4*)&qsm[w][16 * h + 12];
            int d = ((s & 1) << 5) + lane;
            const float* wr = &Wks[d * 132 + 16 * h];
            float4 w0 = *(const float4*)&wr[0];
            float4 w1 = *(const float4*)&wr[4];
            float4 w2 = *(const float4*)&wr[8];
            float4 w3 = *(const float4*)&wr[12];
            float acc = q0.x * w0.x + q0.y * w0.y + q0.z * w0.z + q0.w * w0.w
                      + q1.x * w1.x + q1.y * w1.y + q1.z * w1.z + q1.w * w1.w
                      + q2.x * w2.x + q2.y * w2.y + q2.z * w2.z + q2.w * w2.w
                      + q3.x * w3.x + q3.y * w3.y + q3.z * w3.z + q3.w * w3.w;
            d_U[(size_t)n * 512 + s * 32 + lane] = acc;   // layout == n*512 + h*64 + d
        }
    }
}

// ---------------- fused attention: 2 warps per node, 4 heads per warp (R11 form) ----------------
__global__ void __launch_bounds__(128) attn_kernel(const float* __restrict__ edge_feats,
                                                   const float* __restrict__ Wv,
                                                   int N)
{
    int tid  = threadIdx.x;
    int lane = tid & 31;
    int wid  = tid >> 5;
    int le   = lane & 7;          // lane within head group
    int hh   = lane >> 3;         // head within half (0..3)
    int base = lane & 24;         // first lane of this head group

    int gj = blockIdx.x * 4 + wid;
    int NJ = 2 * N;
    int nw = gridDim.x * 4;

    for (int job = gj; job < NJ; job += nw) {
        int n = job >> 1;
        int W = job & 1;
        int h  = W * 4 + hh;              // global head
        int cb = h * 16 + le * 2;         // 2 owned channels
        int d0 = le * 8;                  // 8 owned ef dims

        int beg = d_rowptr[n], end = d_rowptr[n + 1];

        float2 q = *(const float2*)(d_Q + (size_t)n * 128 + cb);
        const float4* Up = (const float4*)(d_U + (size_t)n * 512 + h * 64 + d0);
        float4 u0 = Up[0], u1 = Up[1];
        float U[8] = {u0.x, u0.y, u0.z, u0.w, u1.x, u1.y, u1.z, u1.w};

        float g[8] = {0.f, 0.f, 0.f, 0.f, 0.f, 0.f, 0.f, 0.f};
        float oo0 = 0.f, oo1 = 0.f, sacc = 0.f;

        int idx = beg;
        for (; idx + 1 < end; idx += 2) {
            int2 esa = d_es[idx];
            int2 esb = d_es[idx + 1];
            const float4* efa = (const float4*)(edge_feats + (size_t)esa.x * 64 + d0);
            const float4* efb = (const float4*)(edge_feats + (size_t)esb.x * 64 + d0);
            float4 a0 = efa[0], a1 = efa[1];
            float4 b0 = efb[0], b1 = efb[1];
            float2 kna = *(const float2*)(d_Kn + (size_t)esa.y * 128 + cb);
            float2 knb = *(const float2*)(d_Kn + (size_t)esb.y * 128 + cb);
            float2 vna = *(const float2*)(d_Vn + (size_t)esa.y * 128 + cb);
            float2 vnb = *(const float2*)(d_Vn + (size_t)esb.y * 128 + cb);

            float pa = q.x * kna.x + q.y * kna.y
                     + a0.x * U[0] + a0.y * U[1] + a0.z * U[2] + a0.w * U[3]
                     + a1.x * U[4] + a1.y * U[5] + a1.z * U[6] + a1.w * U[7];
            float pb = q.x * knb.x + q.y * knb.y
                     + b0.x * U[0] + b0.y * U[1] + b0.z * U[2] + b0.w * U[3]
                     + b1.x * U[4] + b1.y * U[5] + b1.z * U[6] + b1.w * U[7];
            pa += __shfl_xor_sync(FULLMASK, pa, 1);
            pb += __shfl_xor_sync(FULLMASK, pb, 1);
            pa += __shfl_xor_sync(FULLMASK, pa, 2);
            pb += __shfl_xor_sync(FULLMASK, pb, 2);
            pa += __shfl_xor_sync(FULLMASK, pa, 4);
            pb += __shfl_xor_sync(FULLMASK, pb, 4);
            float wa = __expf(0.25f * pa);
            float wb = __expf(0.25f * pb);
            sacc += wa + wb;
            oo0 += wa * vna.x + wb * vnb.x;
            oo1 += wa * vna.y + wb * vnb.y;
            g[0] += wa * a0.x + wb * b0.x;
            g[1] += wa * a0.y + wb * b0.y;
            g[2] += wa * a0.z + wb * b0.z;
            g[3] += wa * a0.w + wb * b0.w;
            g[4] += wa * a1.x + wb * b1.x;
            g[5] += wa * a1.y + wb * b1.y;
            g[6] += wa * a1.z + wb * b1.z;
            g[7] += wa * a1.w + wb * b1.w;
        }
        if (idx < end) {
            int2 es = d_es[idx];
            const float4* ef = (const float4*)(edge_feats + (size_t)es.x * 64 + d0);
            float4 a0 = ef[0], a1 = ef[1];
            float2 kn = *(const float2*)(d_Kn + (size_t)es.y * 128 + cb);
            float2 vn = *(const float2*)(d_Vn + (size_t)es.y * 128 + cb);
            float pa = q.x * kn.x + q.y * kn.y
                     + a0.x * U[0] + a0.y * U[1] + a0.z * U[2] + a0.w * U[3]
                     + a1.x * U[4] + a1.y * U[5] + a1.z * U[6] + a1.w * U[7];
            pa += __shfl_xor_sync(FULLMASK, pa, 1);
            pa += __shfl_xor_sync(FULLMASK, pa, 2);
            pa += __shfl_xor_sync(FULLMASK, pa, 4);
            float wa = __expf(0.25f * pa);
            sacc += wa;
            oo0 += wa * vn.x;
            oo1 += wa * vn.y;
            g[0] += wa * a0.x; g[1] += wa * a0.y; g[2] += wa * a0.z; g[3] += wa * a0.w;
            g[4] += wa * a1.x; g[5] += wa * a1.y; g[6] += wa * a1.z; g[7] += wa * a1.w;
        }

        float ep0 = 0.f, ep1 = 0.f;
#pragma unroll
        for (int t = 0; t < 8; t++) {
#pragma unroll
            for (int j = 0; j < 8; j++) {
                float gv = __shfl_sync(FULLMASK, g[j], base + t);
                float2 w = *(const float2*)(Wv + (size_t)(128 + t * 8 + j) * 128 + cb);
                ep0 += gv * w.x;
                ep1 += gv * w.y;
            }
        }
        float inv = (sacc > 0.f) ? (1.0f / sacc) : 0.f;
        float2 res;
        res.x = (oo0 + ep0) * inv;
        res.y = (oo1 + ep1) * inv;
        *(float2*)(d_Ov + (size_t)n * 128 + cb) = res;
    }
}

// ---------------- host launcher ----------------
extern "C" void kernel_launch(void* const* d_in, const int* in_sizes, int n_in,
                              void* d_out, int out_size)
{
    const float* node_feats = (const float*)d_in[0];
    const float* edge_feats = (const float*)d_in[1];
    const int*   edge_index = (const int*)  d_in[2];
    const float* Wq = (const float*)d_in[3];
    const float* bq = (const float*)d_in[4];
    const float* Wk = (const float*)d_in[5];
    const float* bk = (const float*)d_in[6];
    const float* Wv = (const float*)d_in[7];
    const float* bv = (const float*)d_in[8];
    const float* Wo = (const float*)d_in[9];
    const float* bo = (const float*)d_in[10];
    float* out = (float*)d_out;

    int N = in_sizes[0] / 128;
    int E = in_sizes[1] / 64;
    const int* src = edge_index;
    const int* tgt = edge_index + E;

    float *pQ, *pKn, *pVn, *pO;
    cudaGetSymbolAddress((void**)&pQ,  d_Q);
    cudaGetSymbolAddress((void**)&pKn, d_Kn);
    cudaGetSymbolAddress((void**)&pVn, d_Vn);
    cudaGetSymbolAddress((void**)&pO,  d_Ov);

    int gblocks = (N + 127) / 128;
    int ablocks = (2 * N + 3) / 4;   // 2 warp-jobs per node, 4 warps per block

    deg_kernel<<<(E + 255) / 256, 256>>>(tgt, E);                  // idx 0
    scan_kernel<<<1, 1024>>>(N);                                   // idx 1
    scatter_kernel<<<(E + 255) / 256, 256>>>(src, tgt, E);         // idx 2
    gemm_qkv<<<dim3(gblocks, 3), 256>>>(node_feats, Wq, bq, Wk, bk,
                                        Wv, bv, pQ, pKn, pVn, N);  // idx 3 (ncu slot)
    u_kernel<<<592, 256>>>(Wk, N);                                 // idx 4
    attn_kernel<<<ablocks, 128>>>(edge_feats, Wv, N);              // idx 5
    gemm_k128<<<gblocks, 256>>>(pO, Wo, bo, out, N);               // idx 6
    zero_kernel<<<(N + 255) / 256, 256>>>(N);                      // idx 7: reset for next call
}

// round 17
// speedup vs baseline: 1.4390x; 1.0914x over previous
#include <cuda_runtime.h>
#include <cuda_bf16.h>
#include <cstdint>

#define NN 50000
#define NE 800000
#define FULLMASK 0xffffffffu

// ---------------- static device scratch (no allocation allowed) ----------------
__device__ float d_Q [NN * 128];
__device__ float d_Kn[NN * 128];
__device__ float d_Vn[NN * 128];
__device__ float d_U [(size_t)NN * 512];   // per-node U: [n][h*64 + d]
__device__ __align__(16) __nv_bfloat16 d_Ah [NN * 128];   // node_feats hi
__device__ __align__(16) __nv_bfloat16 d_Al [NN * 128];   // node_feats lo
__device__ __align__(16) __nv_bfloat16 d_Ovh[NN * 128];   // attn output hi
__device__ __align__(16) __nv_bfloat16 d_Ovl[NN * 128];   // attn output lo
// weights: [w][part][n][k] bf16, pre-transposed; w: 0=Wq 1=Wk 2=Wv 3=Wo, part: 0=hi 1=lo
__device__ __align__(16) __nv_bfloat16 d_Wb[4 * 2 * 128 * 128];
__device__ __align__(16) int d_deg[NN];
__device__ int   d_cur[NN];
__device__ __align__(16) int d_rowptr[NN + 4];
__device__ int2  d_es[NE];      // per CSR slot: (edge id, source node)

// ---------------- CSR build ----------------
__global__ void zero_kernel(int n) {
    int i = blockIdx.x * blockDim.x + threadIdx.x;
    if (i < n) { d_deg[i] = 0; d_cur[i] = 0; }
}

__global__ void deg_kernel(const int* __restrict__ tgt, int E) {
    int e = blockIdx.x * blockDim.x + threadIdx.x;
    if (e < E) atomicAdd(&d_deg[tgt[e]], 1);
}

// single-block exclusive scan of d_deg -> d_rowptr, int4-vectorized
__global__ void scan_kernel(int n) {
    __shared__ int ssum[1024];
    int t = threadIdx.x;
    int n4 = n >> 2;
    int C = (n4 + 1023) >> 10;
    int s0 = t * C;
    int s1 = min(s0 + C, n4);
    const int4* deg4 = (const int4*)d_deg;
    int s = 0;
    for (int i = s0; i < s1; i++) {
        int4 v = deg4[i];
        s += v.x + v.y + v.z + v.w;
    }
    ssum[t] = s;
    __syncthreads();
    for (int off = 1; off < 1024; off <<= 1) {
        int v = 0;
        if (t >= off) v = ssum[t - off];
        __syncthreads();
        if (t >= off) ssum[t] += v;
        __syncthreads();
    }
    int run = (t == 0) ? 0 : ssum[t - 1];
    int4* rp4 = (int4*)d_rowptr;
    for (int i = s0; i < s1; i++) {
        int4 v = deg4[i];
        int4 r;
        r.x = run; run += v.x;
        r.y = run; run += v.y;
        r.z = run; run += v.z;
        r.w = run; run += v.w;
        rp4[i] = r;
    }
    if (t == 1023) {
        int run2 = ssum[1023];
        for (int i = n4 * 4; i < n; i++) { d_rowptr[i] = run2; run2 += d_deg[i]; }
        d_rowptr[n] = run2;
    }
}

__global__ void scatter_kernel(const int* __restrict__ src, const int* __restrict__ tgt, int E) {
    int e = blockIdx.x * blockDim.x + threadIdx.x;
    if (e < E) {
        int tg = tgt[e];
        int pos = d_rowptr[tg] + atomicAdd(&d_cur[tg], 1);
        d_es[pos] = make_int2(e, src[e]);
    }
}

// ---------------- conversion kernels ----------------
__device__ __forceinline__ void split_bf16(float v, __nv_bfloat16& h, __nv_bfloat16& l) {
    h = __float2bfloat16_rn(v);
    l = __float2bfloat16_rn(v - __bfloat162float(h));
}

// node_feats fp32 -> hi/lo bf16 (one float4 per thread)
__global__ void __launch_bounds__(256) convert_nf(const float* __restrict__ A, int M) {
    int i = blockIdx.x * blockDim.x + threadIdx.x;
    if (i >= M * 32) return;
    float4 v = ((const float4*)A)[i];
    __nv_bfloat16 h0, h1, h2, h3, l0, l1, l2, l3;
    split_bf16(v.x, h0, l0); split_bf16(v.y, h1, l1);
    split_bf16(v.z, h2, l2); split_bf16(v.w, h3, l3);
    __nv_bfloat162 hh[2] = {{h0, h1}, {h2, h3}};
    __nv_bfloat162 ll[2] = {{l0, l1}, {l2, l3}};
    *(uint2*)&d_Ah[(size_t)i * 4] = *(uint2*)hh;
    *(uint2*)&d_Al[(size_t)i * 4] = *(uint2*)ll;
}

// weights -> pre-transposed hi/lo bf16: d_Wb[w][p][n][k] = split(W[k][n])
__global__ void __launch_bounds__(256) convert_w(const float* __restrict__ Wq,
                                                 const float* __restrict__ Wk,
                                                 const float* __restrict__ Wv,
                                                 const float* __restrict__ Wo) {
    int idx = blockIdx.x * blockDim.x + threadIdx.x;   // 0..65535
    int w = idx >> 14;
    int rem = idx & 16383;
    int n = rem & 127;
    int k = rem >> 7;
    const float* src = (w == 0) ? Wq : (w == 1) ? Wk : (w == 2) ? Wv : Wo;
    float v = src[(size_t)k * 128 + n];
    __nv_bfloat16 h, l;
    split_bf16(v, h, l);
    d_Wb[(size_t)w * 32768 + (size_t)n * 128 + k] = h;
    d_Wb[(size_t)w * 32768 + 16384 + (size_t)n * 128 + k] = l;
}

// ---------------- bf16 split-3 tensor-core GEMM, pre-converted inputs ----------------
__device__ __forceinline__ void mma_bf16(float* c, const uint32_t* a, uint32_t b0, uint32_t b1) {
    asm volatile(
        "mma.sync.aligned.m16n8k16.row.col.f32.bf16.bf16.f32 "
        "{%0,%1,%2,%3}, {%4,%5,%6,%7}, {%8,%9}, {%0,%1,%2,%3};\n"
        : "+f"(c[0]), "+f"(c[1]), "+f"(c[2]), "+f"(c[3])
        : "r"(a[0]), "r"(a[1]), "r"(a[2]), "r"(a[3]), "r"(b0), "r"(b1));
}

#define SMS 40   // smem row stride (bf16 elems): bank-conflict-free fragment loads

// C[M,128] = (Ah+Al)[M,128] @ (Bh+Bl)^T(Bt is [n][k]) + bias, dropping lo*lo.
__device__ __forceinline__ void gemm_tc_v2(const __nv_bfloat16* __restrict__ Ah,
                                           const __nv_bfloat16* __restrict__ Al,
                                           const __nv_bfloat16* __restrict__ Bh,
                                           const __nv_bfloat16* __restrict__ Bl,
                                           const float* __restrict__ bias,
                                           float* __restrict__ C, int M, int bm)
{
    __shared__ __nv_bfloat16 Ahs[128][SMS], Als[128][SMS];
    __shared__ __nv_bfloat16 Bhs[128][SMS], Bls[128][SMS];   // [n][k]

    int tid  = threadIdx.x;
    int lane = tid & 31;
    int wid  = tid >> 5;
    int wm = (wid & 3) * 32;      // warp m-offset
    int wn = (wid >> 2) * 64;     // warp n-offset
    int g  = lane >> 2;           // groupID
    int tg = lane & 3;            // thread-in-group

    float acc[2][8][4];
#pragma unroll
    for (int mi = 0; mi < 2; mi++)
#pragma unroll
        for (int ni = 0; ni < 8; ni++)
#pragma unroll
            for (int c = 0; c < 4; c++) acc[mi][ni][c] = 0.f;

    int r  = tid >> 1;
    int cs = (tid & 1) * 16;
    int ar = bm + r; if (ar >= M) ar = M - 1;

    for (int k0 = 0; k0 < 128; k0 += 32) {
        // stage A chunk: pure 16B copies
        {
            const uint4* ah = (const uint4*)(Ah + (size_t)ar * 128 + k0 + cs);
            const uint4* al = (const uint4*)(Al + (size_t)ar * 128 + k0 + cs);
            *(uint4*)&Ahs[r][cs]     = ah[0];
            *(uint4*)&Ahs[r][cs + 8] = ah[1];
            *(uint4*)&Als[r][cs]     = al[0];
            *(uint4*)&Als[r][cs + 8] = al[1];
        }
        // stage B chunk (Bt already [n][k]): pure 16B copies
        {
            const uint4* bh = (const uint4*)(Bh + (size_t)r * 128 + k0 + cs);
            const uint4* bl = (const uint4*)(Bl + (size_t)r * 128 + k0 + cs);
            *(uint4*)&Bhs[r][cs]     = bh[0];
            *(uint4*)&Bhs[r][cs + 8] = bh[1];
            *(uint4*)&Bls[r][cs]     = bl[0];
            *(uint4*)&Bls[r][cs + 8] = bl[1];
        }
        __syncthreads();

#pragma unroll
        for (int s = 0; s < 32; s += 16) {
            uint32_t ah[2][4], al[2][4];
#pragma unroll
            for (int mi = 0; mi < 2; mi++) {
                int r0 = wm + mi * 16;
                ah[mi][0] = *(const uint32_t*)&Ahs[r0 + g    ][s + 2 * tg];
                ah[mi][1] = *(const uint32_t*)&Ahs[r0 + g + 8][s + 2 * tg];
                ah[mi][2] = *(const uint32_t*)&Ahs[r0 + g    ][s + 2 * tg + 8];
                ah[mi][3] = *(const uint32_t*)&Ahs[r0 + g + 8][s + 2 * tg + 8];
                al[mi][0] = *(const uint32_t*)&Als[r0 + g    ][s + 2 * tg];
                al[mi][1] = *(const uint32_t*)&Als[r0 + g + 8][s + 2 * tg];
                al[mi][2] = *(const uint32_t*)&Als[r0 + g    ][s + 2 * tg + 8];
                al[mi][3] = *(const uint32_t*)&Als[r0 + g + 8][s + 2 * tg + 8];
            }
#pragma unroll
            for (int ni = 0; ni < 8; ni++) {
                int n0 = wn + ni * 8 + g;
                uint32_t bh0 = *(const uint32_t*)&Bhs[n0][s + 2 * tg];
                uint32_t bh1 = *(const uint32_t*)&Bhs[n0][s + 2 * tg + 8];
                uint32_t bl0 = *(const uint32_t*)&Bls[n0][s + 2 * tg];
                uint32_t bl1 = *(const uint32_t*)&Bls[n0][s + 2 * tg + 8];
#pragma unroll
                for (int mi = 0; mi < 2; mi++) {
                    mma_bf16(acc[mi][ni], ah[mi], bh0, bh1);   // hi*hi
                    mma_bf16(acc[mi][ni], al[mi], bh0, bh1);   // lo*hi
                    mma_bf16(acc[mi][ni], ah[mi], bl0, bl1);   // hi*lo
                }
            }
        }
        __syncthreads();
    }

#pragma unroll
    for (int mi = 0; mi < 2; mi++) {
        int r0 = bm + wm + mi * 16 + g;
#pragma unroll
        for (int ni = 0; ni < 8; ni++) {
            int col = wn + ni * 8 + 2 * tg;
            float2 bs = *(const float2*)(bias + col);
            if (r0 < M) {
                float2 v = {acc[mi][ni][0] + bs.x, acc[mi][ni][1] + bs.y};
                *(float2*)(C + (size_t)r0 * 128 + col) = v;
            }
            if (r0 + 8 < M) {
                float2 v = {acc[mi][ni][2] + bs.x, acc[mi][ni][3] + bs.y};
                *(float2*)(C + (size_t)(r0 + 8) * 128 + col) = v;
            }
        }
    }
}

// qkv: A = node_feats (pre-converted), B selected by blockIdx.y from d_Wb
__global__ void __launch_bounds__(256) gemm_qkv(const float* __restrict__ bq,
                                                const float* __restrict__ bk,
                                                const float* __restrict__ bv,
                                                float* __restrict__ Q,
                                                float* __restrict__ K,
                                                float* __restrict__ V, int M)
{
    int w = blockIdx.y;
    const float* bias = (w == 0) ? bq : (w == 1) ? bk : bv;
    float* C = (w == 0) ? Q : (w == 1) ? K : V;
    const __nv_bfloat16* Bh = d_Wb + (size_t)w * 32768;
    const __nv_bfloat16* Bl = Bh + 16384;
    gemm_tc_v2(d_Ah, d_Al, Bh, Bl, bias, C, M, blockIdx.x * 128);
}

// out: A = attn output (hi/lo written by attn), B = Wo
__global__ void __launch_bounds__(256) gemm_out(const float* __restrict__ bo,
                                                float* __restrict__ C, int M)
{
    const __nv_bfloat16* Bh = d_Wb + 3u * 32768;
    const __nv_bfloat16* Bl = Bh + 16384;
    gemm_tc_v2(d_Ovh, d_Ovl, Bh, Bl, bo, C, M, blockIdx.x * 128);
}

// ---------------- U precompute: d_U[n][h*64+d] = sum_c Q[n][16h+c] * Wk[128+d][16h+c] ----
__global__ void __launch_bounds__(256) u_kernel(const float* __restrict__ Wk, int N)
{
    __shared__ float Wks[64 * 132];          // 33.8 KB
    __shared__ float qsm[8][128];            // 4 KB, one row per warp
    int tid = threadIdx.x;
    for (int i = tid; i < 64 * 32; i += blockDim.x) {   // i indexes float4s
        int d = i >> 5;
        int c4 = (i & 31) * 4;
        float4 v = *(const float4*)(Wk + (size_t)(128 + d) * 128 + c4);
        *(float4*)&Wks[d * 132 + c4] = v;
    }
    __syncthreads();

    int lane = tid & 31;
    int w = tid >> 5;
    int gw = blockIdx.x * 8 + w;
    int nw = gridDim.x * 8;

    for (int n = gw; n < N; n += nw) {
        __syncwarp();
        *(float4*)&qsm[w][lane * 4] = *(const float4*)(d_Q + (size_t)n * 128 + lane * 4);
        __syncwarp();
#pragma unroll
        for (int s = 0; s < 16; s++) {
            int h = s >> 1;
            float4 q0 = *(const float4*)&qsm[w][16 * h];
            float4 q1 = *(const float4*)&qsm[w][16 * h + 4];
            float4 q2 = *(const float4*)&qsm[w][16 * h + 8];
            float4 q3 = *(const float4*)&qsm[w][16 * h + 12];
            int d = ((s & 1) << 5) + lane;
            const float* wr = &Wks[d * 132 + 16 * h];
            float4 w0 = *(const float4*)&wr[0];
            float4 w1 = *(const float4*)&wr[4];
            float4 w2 = *(const float4*)&wr[8];
            float4 w3 = *(const float4*)&wr[12];
            float acc = q0.x * w0.x + q0.y * w0.y + q0.z * w0.z + q0.w * w0.w
                      + q1.x * w1.x + q1.y * w1.y + q1.z * w1.z + q1.w * w1.w
                      + q2.x * w2.x + q2.y * w2.y + q2.z * w2.z + q2.w * w2.w
                      + q3.x * w3.x + q3.y * w3.y + q3.z * w3.z + q3.w * w3.w;
            d_U[(size_t)n * 512 + s * 32 + lane] = acc;   // layout == n*512 + h*64 + d
        }
    }
}

// ---------------- fused attention: 2 warps per node, 4 heads per warp ----------------
// Epilogue writes Ov directly as bf16 hi/lo for the tensor-core out-GEMM.
__global__ void __launch_bounds__(128) attn_kernel(const float* __restrict__ edge_feats,
                                                   const float* __restrict__ Wv,
                                                   int N)
{
    int tid  = threadIdx.x;
    int lane = tid & 31;
    int wid  = tid >> 5;
    int le   = lane & 7;          // lane within head group
    int hh   = lane >> 3;         // head within half (0..3)
    int base = lane & 24;         // first lane of this head group

    int gj = blockIdx.x * 4 + wid;
    int NJ = 2 * N;
    int nw = gridDim.x * 4;

    for (int job = gj; job < NJ; job += nw) {
        int n = job >> 1;
        int W = job & 1;
        int h  = W * 4 + hh;              // global head
        int cb = h * 16 + le * 2;         // 2 owned channels
        int d0 = le * 8;                  // 8 owned ef dims

        int beg = d_rowptr[n], end = d_rowptr[n + 1];

        float2 q = *(const float2*)(d_Q + (size_t)n * 128 + cb);
        const float4* Up = (const float4*)(d_U + (size_t)n * 512 + h * 64 + d0);
        float4 u0 = Up[0], u1 = Up[1];
        float U[8] = {u0.x, u0.y, u0.z, u0.w, u1.x, u1.y, u1.z, u1.w};

        float g[8] = {0.f, 0.f, 0.f, 0.f, 0.f, 0.f, 0.f, 0.f};
        float oo0 = 0.f, oo1 = 0.f, sacc = 0.f;

        int idx = beg;
        for (; idx + 1 < end; idx += 2) {
            int2 esa = d_es[idx];
            int2 esb = d_es[idx + 1];
            const float4* efa = (const float4*)(edge_feats + (size_t)esa.x * 64 + d0);
            const float4* efb = (const float4*)(edge_feats + (size_t)esb.x * 64 + d0);
            float4 a0 = efa[0], a1 = efa[1];
            float4 b0 = efb[0], b1 = efb[1];
            float2 kna = *(const float2*)(d_Kn + (size_t)esa.y * 128 + cb);
            float2 knb = *(const float2*)(d_Kn + (size_t)esb.y * 128 + cb);
            float2 vna = *(const float2*)(d_Vn + (size_t)esa.y * 128 + cb);
            float2 vnb = *(const float2*)(d_Vn + (size_t)esb.y * 128 + cb);

            float pa = q.x * kna.x + q.y * kna.y
                     + a0.x * U[0] + a0.y * U[1] + a0.z * U[2] + a0.w * U[3]
                     + a1.x * U[4] + a1.y * U[5] + a1.z * U[6] + a1.w * U[7];
            float pb = q.x * knb.x + q.y * knb.y
                     + b0.x * U[0] + b0.y * U[1] + b0.z * U[2] + b0.w * U[3]
                     + b1.x * U[4] + b1.y * U[5] + b1.z * U[6] + b1.w * U[7];
            pa += __shfl_xor_sync(FULLMASK, pa, 1);
            pb += __shfl_xor_sync(FULLMASK, pb, 1);
            pa += __shfl_xor_sync(FULLMASK, pa, 2);
            pb += __shfl_xor_sync(FULLMASK, pb, 2);
            pa += __shfl_xor_sync(FULLMASK, pa, 4);
            pb += __shfl_xor_sync(FULLMASK, pb, 4);
            float wa = __expf(0.25f * pa);
            float wb = __expf(0.25f * pb);
            sacc += wa + wb;
            oo0 += wa * vna.x + wb * vnb.x;
            oo1 += wa * vna.y + wb * vnb.y;
            g[0] += wa * a0.x + wb * b0.x;
            g[1] += wa * a0.y + wb * b0.y;
            g[2] += wa * a0.z + wb * b0.z;
            g[3] += wa * a0.w + wb * b0.w;
            g[4] += wa * a1.x + wb * b1.x;
            g[5] += wa * a1.y + wb * b1.y;
            g[6] += wa * a1.z + wb * b1.z;
            g[7] += wa * a1.w + wb * b1.w;
        }
        if (idx < end) {
            int2 es = d_es[idx];
            const float4* ef = (const float4*)(edge_feats + (size_t)es.x * 64 + d0);
            float4 a0 = ef[0], a1 = ef[1];
            float2 kn = *(const float2*)(d_Kn + (size_t)es.y * 128 + cb);
            float2 vn = *(const float2*)(d_Vn + (size_t)es.y * 128 + cb);
            float pa = q.x * kn.x + q.y * kn.y
                     + a0.x * U[0] + a0.y * U[1] + a0.z * U[2] + a0.w * U[3]
                     + a1.x * U[4] + a1.y * U[5] + a1.z * U[6] + a1.w * U[7];
            pa += __shfl_xor_sync(FULLMASK, pa, 1);
            pa += __shfl_xor_sync(FULLMASK, pa, 2);
            pa += __shfl_xor_sync(FULLMASK, pa, 4);
            float wa = __expf(0.25f * pa);
            sacc += wa;
            oo0 += wa * vn.x;
            oo1 += wa * vn.y;
            g[0] += wa * a0.x; g[1] += wa * a0.y; g[2] += wa * a0.z; g[3] += wa * a0.w;
            g[4] += wa * a1.x; g[5] += wa * a1.y; g[6] += wa * a1.z; g[7] += wa * a1.w;
        }

        float ep0 = 0.f, ep1 = 0.f;
#pragma unroll
        for (int t = 0; t < 8; t++) {
#pragma unroll
            for (int j = 0; j < 8; j++) {
                float gv = __shfl_sync(FULLMASK, g[j], base + t);
                float2 w = *(const float2*)(Wv + (size_t)(128 + t * 8 + j) * 128 + cb);
                ep0 += gv * w.x;
                ep1 += gv * w.y;
            }
        }
        float inv = (sacc > 0.f) ? (1.0f / sacc) : 0.f;
        float rx = (oo0 + ep0) * inv;
        float ry = (oo1 + ep1) * inv;
        // write Ov as bf16 hi/lo directly (feeds tensor-core out-GEMM)
        __nv_bfloat16 hx = __float2bfloat16_rn(rx);
        __nv_bfloat16 hy = __float2bfloat16_rn(ry);
        __nv_bfloat162 hv = {hx, hy};
        __nv_bfloat162 lv = {__float2bfloat16_rn(rx - __bfloat162float(hx)),
                             __float2bfloat16_rn(ry - __bfloat162float(hy))};
        *(__nv_bfloat162*)&d_Ovh[(size_t)n * 128 + cb] = hv;
        *(__nv_bfloat162*)&d_Ovl[(size_t)n * 128 + cb] = lv;
    }
}

// ---------------- host launcher ----------------
extern "C" void kernel_launch(void* const* d_in, const int* in_sizes, int n_in,
                              void* d_out, int out_size)
{
    const float* node_feats = (const float*)d_in[0];
    const float* edge_feats = (const float*)d_in[1];
    const int*   edge_index = (const int*)  d_in[2];
    const float* Wq = (const float*)d_in[3];
    const float* bq = (const float*)d_in[4];
    const float* Wk = (const float*)d_in[5];
    const float* bk = (const float*)d_in[6];
    const float* Wv = (const float*)d_in[7];
    const float* bv = (const float*)d_in[8];
    const float* Wo = (const float*)d_in[9];
    const float* bo = (const float*)d_in[10];
    float* out = (float*)d_out;

    int N = in_sizes[0] / 128;
    int E = in_sizes[1] / 64;
    const int* src = edge_index;
    const int* tgt = edge_index + E;

    float *pQ, *pKn, *pVn;
    cudaGetSymbolAddress((void**)&pQ,  d_Q);
    cudaGetSymbolAddress((void**)&pKn, d_Kn);
    cudaGetSymbolAddress((void**)&pVn, d_Vn);

    int gblocks = (N + 127) / 128;
    int ablocks = (2 * N + 3) / 4;   // 2 warp-jobs per node, 4 warps per block

    deg_kernel<<<(E + 255) / 256, 256>>>(tgt, E);                    // idx 0
    convert_nf<<<(N * 32 + 255) / 256, 256>>>(node_feats, N);        // idx 1
    convert_w<<<256, 256>>>(Wq, Wk, Wv, Wo);                         // idx 2
    gemm_qkv<<<dim3(gblocks, 3), 256>>>(bq, bk, bv, pQ, pKn, pVn, N); // idx 3 (ncu slot)
    scan_kernel<<<1, 1024>>>(N);                                     // idx 4
    scatter_kernel<<<(E + 255) / 256, 256>>>(src, tgt, E);           // idx 5
    u_kernel<<<592, 256>>>(Wk, N);                                   // idx 6
    attn_kernel<<<ablocks, 128>>>(edge_feats, Wv, N);                // idx 7
    gemm_out<<<gblocks, 256>>>(bo, out, N);                          // idx 8
    zero_kernel<<<(N + 255) / 256, 256>>>(N);                        // idx 9: reset for next call
}